// round 1
// baseline (speedup 1.0000x reference)
#include <cuda_runtime.h>
#include <math.h>

#define Bn 16
#define Qn 128
#define Kn 4096
#define Dn 512
#define Hn 8
#define Cn 64
#define MQn 32
#define KEEPN 33   // MQ + 1

// ---------------- scratch (device globals; no allocation allowed) ----------------
static __device__ float g_q   [(size_t)Bn*Qn*Dn];          //  4 MB   q projections [B,Q,D]
static __device__ float g_k   [(size_t)Bn*Kn*Dn];          // 134 MB  k projections [B,K,D]
static __device__ float g_dots[(size_t)Bn*Hn*Qn*Kn];       // 256 MB  [B,H,Q,K]
static __device__ float g_attn[(size_t)Bn*Hn*KEEPN*Kn];    //  66 MB  unnormalized attn [B,H,33,K]
static __device__ float g_score[Bn*(Qn-1)];
static __device__ int   g_keep [Bn*KEEPN];
static __device__ float g_rowsum[Bn*Hn*KEEPN];
static __device__ float g_s1f [(size_t)Bn*Hn*KEEPN*Dn];    // attn @ ctx      [B, H*33, D]
static __device__ float g_s1e [(size_t)Bn*Hn*KEEPN*Dn];    // attn @ ctx_enc  [B, H*33, D]
static __device__ float g_pref[(size_t)Bn*KEEPN*Dn];       // per-head contracted feats [B,33,D]
static __device__ float g_pree[(size_t)Bn*KEEPN*Dn];

// ---------------- generic batched SGEMM ----------------
// C[n, j] = scale * sum_m (A1[n,m] (+A2[n,m])) * W(j,m)   (+ bias[j])
// transB=0: W(j,m) = W[j*ldw + m]   (NT, weight-style)
// transB=1: W(j,m) = W[m*ldw + j]   (NN, ctx-style)
// Batch via blockIdx.z: b = z/zdiv, h = z%zdiv; pointer offsets b*s?b + h*s?h.
__global__ void __launch_bounds__(256) gemm_kernel(
    const float* __restrict__ A1, const float* __restrict__ A2, int lda,
    const float* __restrict__ W, int ldw, int transB,
    const float* __restrict__ bias,
    float* __restrict__ C, int ldc,
    int nrows, int ncols, int kdim, float scale, int zdiv,
    long long sAb, long long sAh, long long sWb, long long sWh,
    long long sCb, long long sCh)
{
    __shared__ float As[8][128];
    __shared__ float Ws[8][128];

    int z = blockIdx.z;
    int b = z / zdiv, h = z - b * zdiv;
    A1 += (long long)b * sAb + (long long)h * sAh;
    if (A2) A2 += (long long)b * sAb + (long long)h * sAh;
    W  += (long long)b * sWb + (long long)h * sWh;
    C  += (long long)b * sCb + (long long)h * sCh;

    const int tid  = threadIdx.x;
    const int row0 = blockIdx.y * 128;
    const int col0 = blockIdx.x * 128;
    const int tx = tid & 15, ty = tid >> 4;

    float acc[8][8];
    #pragma unroll
    for (int i = 0; i < 8; i++)
        #pragma unroll
        for (int j = 0; j < 8; j++) acc[i][j] = 0.f;

    const int alr = tid >> 1;          // 0..127 tile row
    const int alc = (tid & 1) * 4;     // 0 or 4 within the 8-wide k-slab
    const int nwr = tid >> 5;          // NN: k-row within slab (0..7)
    const int nwc = (tid & 31) * 4;    // NN: col within tile

    for (int m0 = 0; m0 < kdim; m0 += 8) {
        {   // A tile (optionally fused A1+A2)
            int gr = row0 + alr;
            float4 v = make_float4(0.f, 0.f, 0.f, 0.f);
            if (gr < nrows) {
                v = *(const float4*)(A1 + (long long)gr * lda + m0 + alc);
                if (A2) {
                    float4 v2 = *(const float4*)(A2 + (long long)gr * lda + m0 + alc);
                    v.x += v2.x; v.y += v2.y; v.z += v2.z; v.w += v2.w;
                }
            }
            As[alc+0][alr] = v.x; As[alc+1][alr] = v.y;
            As[alc+2][alr] = v.z; As[alc+3][alr] = v.w;
        }
        if (!transB) { // NT
            int gr = col0 + alr;
            float4 v = make_float4(0.f, 0.f, 0.f, 0.f);
            if (gr < ncols) v = *(const float4*)(W + (long long)gr * ldw + m0 + alc);
            Ws[alc+0][alr] = v.x; Ws[alc+1][alr] = v.y;
            Ws[alc+2][alr] = v.z; Ws[alc+3][alr] = v.w;
        } else {       // NN
            int gc = col0 + nwc;
            float4 v = make_float4(0.f, 0.f, 0.f, 0.f);
            if (gc < ncols) v = *(const float4*)(W + (long long)(m0 + nwr) * ldw + gc);
            *(float4*)&Ws[nwr][nwc] = v;
        }
        __syncthreads();
        #pragma unroll
        for (int m = 0; m < 8; m++) {
            float a[8], w[8];
            *(float4*)&a[0] = *(const float4*)&As[m][ty*8];
            *(float4*)&a[4] = *(const float4*)&As[m][ty*8+4];
            *(float4*)&w[0] = *(const float4*)&Ws[m][tx*8];
            *(float4*)&w[4] = *(const float4*)&Ws[m][tx*8+4];
            #pragma unroll
            for (int i = 0; i < 8; i++)
                #pragma unroll
                for (int j = 0; j < 8; j++)
                    acc[i][j] += a[i] * w[j];
        }
        __syncthreads();
    }

    #pragma unroll
    for (int i = 0; i < 8; i++) {
        int gr = row0 + ty*8 + i;
        if (gr >= nrows) continue;
        #pragma unroll
        for (int j = 0; j < 8; j++) {
            int gc = col0 + tx*8 + j;
            if (gc >= ncols) continue;
            float v = acc[i][j] * scale;
            if (bias) v += bias[gc];
            C[(long long)gr * ldc + gc] = v;
        }
    }
}

// ---------------- per-launch state reset ----------------
__global__ void init_kernel() {
    for (int i = threadIdx.x; i < Bn*(Qn-1); i += 256) g_score[i] = 0.f;
    for (int i = threadIdx.x; i < Bn*Hn*KEEPN; i += 256) g_rowsum[i] = 0.f;
}

// ---------------- query scoring ----------------
// Per (b,h,k) column: softmax over queries 1..127, then max-reduce each query's
// value into g_score[b, q-1] across all (h,k). Grid (K/128, H, B), 128 threads.
__global__ void score_kernel() {
    int b = blockIdx.z, h = blockIdx.y;
    int k = blockIdx.x * 128 + threadIdx.x;
    const float* col = g_dots + ((size_t)((b*Hn + h) * Qn)) * Kn + k;
    float m = -INFINITY, s = 0.f;
    for (int q = 1; q < Qn; q++) {
        float d  = col[(size_t)q * Kn];
        float nm = fmaxf(m, d);
        s = s * expf(m - nm) + expf(d - nm);
        m = nm;
    }
    float inv = 1.f / s;
    __shared__ float wmax[4];
    int lane = threadIdx.x & 31, wid = threadIdx.x >> 5;
    for (int q = 1; q < Qn; q++) {
        float v = expf(col[(size_t)q * Kn] - m) * inv;
        #pragma unroll
        for (int o = 16; o > 0; o >>= 1)
            v = fmaxf(v, __shfl_xor_sync(0xffffffffu, v, o));
        if (lane == 0) wmax[wid] = v;
        __syncthreads();
        if (threadIdx.x == 0) {
            float bm = fmaxf(fmaxf(wmax[0], wmax[1]), fmaxf(wmax[2], wmax[3]));
            atomicMax((int*)&g_score[b*(Qn-1) + q - 1], __float_as_int(bm)); // scores > 0
        }
        __syncthreads();
    }
}

// ---------------- top-32 selection (ties -> lower index, matching lax.top_k) ----------------
__global__ void topk_kernel() {
    int b = blockIdx.x;
    int t = threadIdx.x;   // 128
    __shared__ float sv[128];
    __shared__ float rv[128];
    __shared__ int   ri[128];
    sv[t] = (t < Qn-1) ? g_score[b*(Qn-1) + t] : -INFINITY;
    __syncthreads();
    for (int r = 0; r < MQn; r++) {
        rv[t] = sv[t]; ri[t] = t;
        __syncthreads();
        for (int off = 64; off > 0; off >>= 1) {
            if (t < off) {
                float v2 = rv[t+off]; int i2 = ri[t+off];
                if (v2 > rv[t] || (v2 == rv[t] && i2 < ri[t])) { rv[t] = v2; ri[t] = i2; }
            }
            __syncthreads();
        }
        int win = ri[0];
        if (t == 0) g_keep[b*KEEPN + 1 + r] = win + 1;
        if (t == win) sv[t] = -INFINITY;
        __syncthreads();
    }
    if (t == 0) g_keep[b*KEEPN] = 0;
}

// ---------------- gather + competitive softmax (query axis), rowsums ----------------
// Writes UNNORMALIZED attn (key-renorm deferred past the AV GEMM, it's linear).
__global__ void softmax_kernel() {
    int b = blockIdx.z, h = blockIdx.y;
    int k = blockIdx.x * 128 + threadIdx.x;
    __shared__ int   kq[KEEPN];
    __shared__ float rs[KEEPN];
    if (threadIdx.x < KEEPN) {
        kq[threadIdx.x] = g_keep[b*KEEPN + threadIdx.x];
        rs[threadIdx.x] = 0.f;
    }
    __syncthreads();
    const float* base = g_dots + ((size_t)((b*Hn + h) * Qn)) * Kn + k;
    float d[KEEPN];
    float m = -INFINITY;
    #pragma unroll
    for (int j = 0; j < KEEPN; j++) {
        d[j] = base[(size_t)kq[j] * Kn];
        m = fmaxf(m, d[j]);
    }
    float s = 0.f;
    #pragma unroll
    for (int j = 0; j < KEEPN; j++) { d[j] = expf(d[j] - m); s += d[j]; }
    float inv = 1.f / s;
    float* outp = g_attn + ((size_t)((b*Hn + h) * KEEPN)) * Kn + k;
    int lane = threadIdx.x & 31;
    #pragma unroll
    for (int j = 0; j < KEEPN; j++) {
        float a = d[j] * inv;
        outp[(size_t)j * Kn] = a;
        float w = a;
        #pragma unroll
        for (int o = 16; o > 0; o >>= 1) w += __shfl_xor_sync(0xffffffffu, w, o);
        if (lane == 0) atomicAdd(&rs[j], w);
    }
    __syncthreads();
    if (threadIdx.x < KEEPN)
        atomicAdd(&g_rowsum[(b*Hn + h)*KEEPN + threadIdx.x], rs[threadIdx.x]);
}

// ---------------- key-axis renormalization of S1 = attn @ ctx ----------------
__global__ void normalize_kernel() {
    int idx = blockIdx.x * 256 + threadIdx.x;
    const int total = Bn*Hn*KEEPN*Dn;
    if (idx >= total) return;
    int r = idx / Dn;                 // = b*264 + h*33 + j  (matches rowsum layout)
    float inv = 1.f / (g_rowsum[r] + 1e-8f);
    g_s1f[idx] *= inv;
    g_s1e[idx] *= inv;
}

__global__ void finalize_keep_kernel(float* outp) {
    int i = blockIdx.x * 256 + threadIdx.x;
    if (i < Bn*KEEPN) outp[i] = (float)g_keep[i];
}

// ---------------- launch ----------------
extern "C" void kernel_launch(void* const* d_in, const int* in_sizes, int n_in,
                              void* d_out, int out_size) {
    const float* slots     = (const float*)d_in[0];
    const float* slots_enc = (const float*)d_in[1];
    const float* ctx       = (const float*)d_in[2];
    const float* ctx_enc   = (const float*)d_in[3];
    const float* Wq  = (const float*)d_in[4];
    const float* Wk  = (const float*)d_in[5];
    const float* Wf  = (const float*)d_in[6];
    const float* We  = (const float*)d_in[7];
    const float* Wof = (const float*)d_in[8];
    const float* bof = (const float*)d_in[9];
    const float* Woe = (const float*)d_in[10];
    const float* boe = (const float*)d_in[11];
    float* outp = (float*)d_out;

    float *pq, *pk, *pdots, *pattn, *ps1f, *ps1e, *ppref, *ppree;
    cudaGetSymbolAddress((void**)&pq,    g_q);
    cudaGetSymbolAddress((void**)&pk,    g_k);
    cudaGetSymbolAddress((void**)&pdots, g_dots);
    cudaGetSymbolAddress((void**)&pattn, g_attn);
    cudaGetSymbolAddress((void**)&ps1f,  g_s1f);
    cudaGetSymbolAddress((void**)&ps1e,  g_s1e);
    cudaGetSymbolAddress((void**)&ppref, g_pref);
    cudaGetSymbolAddress((void**)&ppree, g_pree);

    dim3 T(256);

    init_kernel<<<1, 256>>>();

    // q = (slots + slots_enc) @ Wq^T            [2048 x 512]
    gemm_kernel<<<dim3(4, 16, 1), T>>>(slots, slots_enc, Dn, Wq, Dn, 0, nullptr,
        pq, Dn, Bn*Qn, Dn, Dn, 1.f, 1, 0, 0, 0, 0, 0, 0);

    // k = (ctx + ctx_enc) @ Wk^T                [65536 x 512]
    gemm_kernel<<<dim3(4, 512, 1), T>>>(ctx, ctx_enc, Dn, Wk, Dn, 0, nullptr,
        pk, Dn, Bn*Kn, Dn, Dn, 1.f, 1, 0, 0, 0, 0, 0, 0);

    // dots[b,h,q,k] = (q/8) . k                 batched (b,h): [128 x 4096 x 64]
    gemm_kernel<<<dim3(Kn/128, 1, Bn*Hn), T>>>(pq, nullptr, Dn, pk, Dn, 0, nullptr,
        pdots, Kn, Qn, Kn, Cn, 0.125f, Hn,
        (long long)Qn*Dn, 64, (long long)Kn*Dn, 64,
        (long long)Hn*Qn*Kn, (long long)Qn*Kn);

    score_kernel  <<<dim3(Kn/128, Hn, Bn), 128>>>();
    topk_kernel   <<<Bn, 128>>>();
    softmax_kernel<<<dim3(Kn/128, Hn, Bn), 128>>>();

    // S1f = attn_un @ ctx, S1e = attn_un @ ctx_enc   batched b: [264 x 512 x 4096]
    gemm_kernel<<<dim3(4, 3, Bn), T>>>(pattn, nullptr, Kn, ctx, Dn, 1, nullptr,
        ps1f, Dn, Hn*KEEPN, Dn, Kn, 1.f, 1,
        (long long)Hn*KEEPN*Kn, 0, (long long)Kn*Dn, 0,
        (long long)Hn*KEEPN*Dn, 0);
    gemm_kernel<<<dim3(4, 3, Bn), T>>>(pattn, nullptr, Kn, ctx_enc, Dn, 1, nullptr,
        ps1e, Dn, Hn*KEEPN, Dn, Kn, 1.f, 1,
        (long long)Hn*KEEPN*Kn, 0, (long long)Kn*Dn, 0,
        (long long)Hn*KEEPN*Dn, 0);

    normalize_kernel<<<(Bn*Hn*KEEPN*Dn + 255)/256, 256>>>();

    // per-head contraction with Wf/We rows:  pref[b,j,h*64+c] = S1n[b,h,j,:] . Wf[h*64+c,:]
    gemm_kernel<<<dim3(1, 1, Bn*Hn), T>>>(ps1f, nullptr, Dn, Wf, Dn, 0, nullptr,
        ppref, Dn, KEEPN, Cn, Dn, 1.f, Hn,
        (long long)Hn*KEEPN*Dn, (long long)KEEPN*Dn,
        0, (long long)Cn*Dn,
        (long long)KEEPN*Dn, (long long)Cn);
    gemm_kernel<<<dim3(1, 1, Bn*Hn), T>>>(ps1e, nullptr, Dn, We, Dn, 0, nullptr,
        ppree, Dn, KEEPN, Cn, Dn, 1.f, Hn,
        (long long)Hn*KEEPN*Dn, (long long)KEEPN*Dn,
        0, (long long)Cn*Dn,
        (long long)KEEPN*Dn, (long long)Cn);

    // output projections straight into d_out
    gemm_kernel<<<dim3(4, 5, 1), T>>>(ppref, nullptr, Dn, Wof, Dn, 0, bof,
        outp, Dn, Bn*KEEPN, Dn, Dn, 1.f, 1, 0, 0, 0, 0, 0, 0);
    gemm_kernel<<<dim3(4, 5, 1), T>>>(ppree, nullptr, Dn, Woe, Dn, 0, boe,
        outp + (size_t)Bn*KEEPN*Dn, Dn, Bn*KEEPN, Dn, Dn, 1.f, 1, 0, 0, 0, 0, 0, 0);

    finalize_keep_kernel<<<3, 256>>>(outp + 2*(size_t)Bn*KEEPN*Dn);
}

// round 2
// speedup vs baseline: 1.2947x; 1.2947x over previous
#include <cuda_runtime.h>
#include <math.h>
#include <stdint.h>

#define Bn 16
#define Qn 128
#define Kn 4096
#define Dn 512
#define Hn 8
#define Cn 64
#define MQn 32
#define KEEPN 33   // MQ + 1

// ---------------- scratch (device globals; no allocation allowed) ----------------
static __device__ float g_q   [(size_t)Bn*Qn*Dn];            //  4 MB  q projections [B,Q,D]
static __device__ float g_qk  [(size_t)Bn*Hn*Qn*Dn];         // 32 MB  q@Wk per head [B,H,Q,D]
static __device__ float g_dots[(size_t)Bn*Hn*Qn*Kn];         // 256 MB [B,H,Q,K]
static __device__ float g_attn[(size_t)Bn*Hn*KEEPN*Kn];      //  66 MB unnormalized attn
static __device__ float g_score[Bn*(Qn-1)];
static __device__ int   g_keep [Bn*KEEPN];
static __device__ float g_rowsum[Bn*Hn*KEEPN];
static __device__ float g_s1f [(size_t)Bn*Hn*KEEPN*Dn];
static __device__ float g_s1e [(size_t)Bn*Hn*KEEPN*Dn];
static __device__ float g_pref[(size_t)Bn*KEEPN*Dn];
static __device__ float g_pree[(size_t)Bn*KEEPN*Dn];

// ---------------- 3xTF32 tensor-core GEMM ----------------
// C[r,c] = scale * sum_k Aeff[r,k] * Beff[k,c]  (+ bias[c])
//   Aeff = A1 (+A2 if non-null), row-major lda
//   transB=0 (NT): Beff[k,c] = W1[c*ldw + k] (+W2)
//   transB=1 (NN): Beff[k,c] = W1[k*ldw + c] (+W2)
// Batched over blockIdx.z: b = z/zdiv, h = z%zdiv with per-operand strides.
// fp32 inputs split into hi/lo tf32; 3 mma products -> ~fp32 accuracy.

#define BM 128
#define BN 128
#define BKt 16
#define LDT 132   // BM + 4 pad (conflict-free frag loads)

__device__ __forceinline__ void split_tf32(float f, uint32_t& hi, uint32_t& lo) {
    asm("cvt.rna.tf32.f32 %0, %1;" : "=r"(hi) : "f"(f));
    float r = f - __uint_as_float(hi);
    asm("cvt.rna.tf32.f32 %0, %1;" : "=r"(lo) : "f"(r));
}

__device__ __forceinline__ void mma8(float* d, const uint32_t* a, const uint32_t* b) {
    asm volatile(
        "mma.sync.aligned.m16n8k8.row.col.f32.tf32.tf32.f32 "
        "{%0,%1,%2,%3}, {%4,%5,%6,%7}, {%8,%9}, {%0,%1,%2,%3};"
        : "+f"(d[0]), "+f"(d[1]), "+f"(d[2]), "+f"(d[3])
        : "r"(a[0]), "r"(a[1]), "r"(a[2]), "r"(a[3]), "r"(b[0]), "r"(b[1]));
}

__global__ void __launch_bounds__(256, 2) mma_gemm(
    const float* __restrict__ A1, const float* __restrict__ A2, int lda,
    const float* __restrict__ W1, const float* __restrict__ W2, int ldw, int transB,
    const float* __restrict__ bias,
    float* __restrict__ C, int ldc,
    int nrows, int ncols, int kdim, float scale, int zdiv,
    long long sAb, long long sAh, long long sWb, long long sWh,
    long long sCb, long long sCh)
{
    __shared__ __align__(16) float As[BKt][LDT];
    __shared__ __align__(16) float Bs[BKt][LDT];

    int z = blockIdx.z;
    int b = z / zdiv, h = z - b * zdiv;
    A1 += (long long)b * sAb + (long long)h * sAh;
    if (A2) A2 += (long long)b * sAb + (long long)h * sAh;
    W1 += (long long)b * sWb + (long long)h * sWh;
    if (W2) W2 += (long long)b * sWb + (long long)h * sWh;
    C  += (long long)b * sCb + (long long)h * sCh;

    const int tid  = threadIdx.x;
    const int lane = tid & 31;
    const int warp = tid >> 5;
    const int wr = warp >> 2;        // 0..1  (64-row warp tile)
    const int wc = warp & 3;         // 0..3  (32-col warp tile)
    const int g  = lane >> 2;        // 0..7
    const int t  = lane & 3;         // 0..3
    const int row0 = blockIdx.y * BM;
    const int col0 = blockIdx.x * BN;

    float acc[4][4][4];
    #pragma unroll
    for (int mi = 0; mi < 4; mi++)
        #pragma unroll
        for (int ni = 0; ni < 4; ni++)
            #pragma unroll
            for (int j = 0; j < 4; j++) acc[mi][ni][j] = 0.f;

    for (int k0 = 0; k0 < kdim; k0 += BKt) {
        // ---- A tile: [BM x BKt] -> As[k][row]
        #pragma unroll
        for (int it = 0; it < 2; it++) {
            int i = it * 256 + tid;
            int r = i >> 2, kc = (i & 3) * 4;
            float4 v = make_float4(0.f, 0.f, 0.f, 0.f);
            if (row0 + r < nrows) {
                v = *(const float4*)(A1 + (long long)(row0 + r) * lda + k0 + kc);
                if (A2) {
                    float4 v2 = *(const float4*)(A2 + (long long)(row0 + r) * lda + k0 + kc);
                    v.x += v2.x; v.y += v2.y; v.z += v2.z; v.w += v2.w;
                }
            }
            As[kc+0][r] = v.x; As[kc+1][r] = v.y;
            As[kc+2][r] = v.z; As[kc+3][r] = v.w;
        }
        // ---- B tile -> Bs[k][col]
        if (!transB) {
            #pragma unroll
            for (int it = 0; it < 2; it++) {
                int i = it * 256 + tid;
                int r = i >> 2, kc = (i & 3) * 4;
                float4 v = make_float4(0.f, 0.f, 0.f, 0.f);
                if (col0 + r < ncols) {
                    v = *(const float4*)(W1 + (long long)(col0 + r) * ldw + k0 + kc);
                    if (W2) {
                        float4 v2 = *(const float4*)(W2 + (long long)(col0 + r) * ldw + k0 + kc);
                        v.x += v2.x; v.y += v2.y; v.z += v2.z; v.w += v2.w;
                    }
                }
                Bs[kc+0][r] = v.x; Bs[kc+1][r] = v.y;
                Bs[kc+2][r] = v.z; Bs[kc+3][r] = v.w;
            }
        } else {
            #pragma unroll
            for (int it = 0; it < 2; it++) {
                int i = it * 256 + tid;
                int kr = i >> 5, n4 = (i & 31) * 4;
                float4 v = make_float4(0.f, 0.f, 0.f, 0.f);
                if (col0 + n4 + 3 < ncols) {
                    v = *(const float4*)(W1 + (long long)(k0 + kr) * ldw + col0 + n4);
                    if (W2) {
                        float4 v2 = *(const float4*)(W2 + (long long)(k0 + kr) * ldw + col0 + n4);
                        v.x += v2.x; v.y += v2.y; v.z += v2.z; v.w += v2.w;
                    }
                }
                *(float4*)&Bs[kr][n4] = v;
            }
        }
        __syncthreads();

        #pragma unroll
        for (int ks = 0; ks < BKt; ks += 8) {
            // B fragments for the 4 n-tiles of this warp
            uint32_t bhi[4][2], blo[4][2];
            #pragma unroll
            for (int ni = 0; ni < 4; ni++) {
                int c = wc * 32 + ni * 8 + g;
                split_tf32(Bs[ks + t][c],     bhi[ni][0], blo[ni][0]);
                split_tf32(Bs[ks + t + 4][c], bhi[ni][1], blo[ni][1]);
            }
            #pragma unroll
            for (int mi = 0; mi < 4; mi++) {
                int r = wr * 64 + mi * 16 + g;
                uint32_t ahi[4], alo[4];
                split_tf32(As[ks + t][r],         ahi[0], alo[0]);
                split_tf32(As[ks + t][r + 8],     ahi[1], alo[1]);
                split_tf32(As[ks + t + 4][r],     ahi[2], alo[2]);
                split_tf32(As[ks + t + 4][r + 8], ahi[3], alo[3]);
                #pragma unroll
                for (int ni = 0; ni < 4; ni++) {
                    mma8(acc[mi][ni], ahi, bhi[ni]);
                    mma8(acc[mi][ni], alo, bhi[ni]);
                    mma8(acc[mi][ni], ahi, blo[ni]);
                }
            }
        }
        __syncthreads();
    }

    // ---- epilogue
    #pragma unroll
    for (int mi = 0; mi < 4; mi++) {
        #pragma unroll
        for (int ni = 0; ni < 4; ni++) {
            int r = row0 + wr * 64 + mi * 16 + g;
            int c = col0 + wc * 32 + ni * 8 + 2 * t;
            #pragma unroll
            for (int j = 0; j < 4; j++) {
                int rr = r + (j >> 1) * 8;
                int cc = c + (j & 1);
                if (rr < nrows && cc < ncols) {
                    float v = acc[mi][ni][j] * scale;
                    if (bias) v += bias[cc];
                    C[(long long)rr * ldc + cc] = v;
                }
            }
        }
    }
}

// ---------------- per-launch state reset ----------------
__global__ void init_kernel() {
    for (int i = threadIdx.x; i < Bn*(Qn-1); i += 256) g_score[i] = 0.f;
    for (int i = threadIdx.x; i < Bn*Hn*KEEPN; i += 256) g_rowsum[i] = 0.f;
}

// ---------------- query scoring ----------------
// Per column (b,h,k): softmax over queries 1..127 (no max-shift; dots bounded),
// then per-q block max via shuffles, one global atomicMax per q per block.
__global__ void score_kernel() {
    int b = blockIdx.z, h = blockIdx.y;
    int k = blockIdx.x * 128 + threadIdx.x;
    const float* col = g_dots + ((size_t)((b*Hn + h) * Qn)) * Kn + k;
    float s = 0.f;
    #pragma unroll 4
    for (int q = 1; q < Qn; q++) s += __expf(col[(size_t)q * Kn]);
    float inv = 1.f / s;
    __shared__ float wm[4][Qn];
    int lane = threadIdx.x & 31, wid = threadIdx.x >> 5;
    for (int q = 1; q < Qn; q++) {
        float v = __expf(col[(size_t)q * Kn]) * inv;
        #pragma unroll
        for (int o = 16; o > 0; o >>= 1)
            v = fmaxf(v, __shfl_xor_sync(0xffffffffu, v, o));
        if (lane == 0) wm[wid][q] = v;
    }
    __syncthreads();
    int q = threadIdx.x;
    if (q >= 1 && q < Qn) {
        float m = fmaxf(fmaxf(wm[0][q], wm[1][q]), fmaxf(wm[2][q], wm[3][q]));
        atomicMax((int*)&g_score[b*(Qn-1) + q - 1], __float_as_int(m)); // scores > 0
    }
}

// ---------------- top-32 selection (ties -> lower index) ----------------
__global__ void topk_kernel() {
    int b = blockIdx.x;
    int t = threadIdx.x;   // 128
    __shared__ float sv[128];
    __shared__ float rv[128];
    __shared__ int   ri[128];
    sv[t] = (t < Qn-1) ? g_score[b*(Qn-1) + t] : -INFINITY;
    __syncthreads();
    for (int r = 0; r < MQn; r++) {
        rv[t] = sv[t]; ri[t] = t;
        __syncthreads();
        for (int off = 64; off > 0; off >>= 1) {
            if (t < off) {
                float v2 = rv[t+off]; int i2 = ri[t+off];
                if (v2 > rv[t] || (v2 == rv[t] && i2 < ri[t])) { rv[t] = v2; ri[t] = i2; }
            }
            __syncthreads();
        }
        int win = ri[0];
        if (t == 0) g_keep[b*KEEPN + 1 + r] = win + 1;
        if (t == win) sv[t] = -INFINITY;
        __syncthreads();
    }
    if (t == 0) g_keep[b*KEEPN] = 0;
}

// ---------------- gather + competitive softmax (query axis), rowsums ----------------
__global__ void softmax_kernel() {
    int b = blockIdx.z, h = blockIdx.y;
    int k = blockIdx.x * 128 + threadIdx.x;
    __shared__ int   kq[KEEPN];
    __shared__ float rs[KEEPN];
    if (threadIdx.x < KEEPN) {
        kq[threadIdx.x] = g_keep[b*KEEPN + threadIdx.x];
        rs[threadIdx.x] = 0.f;
    }
    __syncthreads();
    const float* base = g_dots + ((size_t)((b*Hn + h) * Qn)) * Kn + k;
    float d[KEEPN];
    float m = -INFINITY;
    #pragma unroll
    for (int j = 0; j < KEEPN; j++) {
        d[j] = base[(size_t)kq[j] * Kn];
        m = fmaxf(m, d[j]);
    }
    float s = 0.f;
    #pragma unroll
    for (int j = 0; j < KEEPN; j++) { d[j] = __expf(d[j] - m); s += d[j]; }
    float inv = 1.f / s;
    float* outp = g_attn + ((size_t)((b*Hn + h) * KEEPN)) * Kn + k;
    int lane = threadIdx.x & 31;
    #pragma unroll
    for (int j = 0; j < KEEPN; j++) {
        float a = d[j] * inv;
        outp[(size_t)j * Kn] = a;
        float w = a;
        #pragma unroll
        for (int o = 16; o > 0; o >>= 1) w += __shfl_xor_sync(0xffffffffu, w, o);
        if (lane == 0) atomicAdd(&rs[j], w);
    }
    __syncthreads();
    if (threadIdx.x < KEEPN)
        atomicAdd(&g_rowsum[(b*Hn + h)*KEEPN + threadIdx.x], rs[threadIdx.x]);
}

// ---------------- key-axis renormalization of S1 ----------------
__global__ void normalize_kernel() {
    int idx = blockIdx.x * 256 + threadIdx.x;
    const int total = Bn*Hn*KEEPN*Dn;
    if (idx >= total) return;
    int r = idx / Dn;
    float inv = 1.f / (g_rowsum[r] + 1e-8f);
    g_s1f[idx] *= inv;
    g_s1e[idx] *= inv;
}

__global__ void finalize_keep_kernel(float* outp) {
    int i = blockIdx.x * 256 + threadIdx.x;
    if (i < Bn*KEEPN) outp[i] = (float)g_keep[i];
}

// ---------------- launch ----------------
extern "C" void kernel_launch(void* const* d_in, const int* in_sizes, int n_in,
                              void* d_out, int out_size) {
    const float* slots     = (const float*)d_in[0];
    const float* slots_enc = (const float*)d_in[1];
    const float* ctx       = (const float*)d_in[2];
    const float* ctx_enc   = (const float*)d_in[3];
    const float* Wq  = (const float*)d_in[4];
    const float* Wk  = (const float*)d_in[5];
    const float* Wf  = (const float*)d_in[6];
    const float* We  = (const float*)d_in[7];
    const float* Wof = (const float*)d_in[8];
    const float* bof = (const float*)d_in[9];
    const float* Woe = (const float*)d_in[10];
    const float* boe = (const float*)d_in[11];
    float* outp = (float*)d_out;

    float *pq, *pqk, *pdots, *pattn, *ps1f, *ps1e, *ppref, *ppree;
    cudaGetSymbolAddress((void**)&pq,    g_q);
    cudaGetSymbolAddress((void**)&pqk,   g_qk);
    cudaGetSymbolAddress((void**)&pdots, g_dots);
    cudaGetSymbolAddress((void**)&pattn, g_attn);
    cudaGetSymbolAddress((void**)&ps1f,  g_s1f);
    cudaGetSymbolAddress((void**)&ps1e,  g_s1e);
    cudaGetSymbolAddress((void**)&ppref, g_pref);
    cudaGetSymbolAddress((void**)&ppree, g_pree);

    dim3 T(256);

    init_kernel<<<1, 256>>>();

    // q = (slots + slots_enc) @ Wq^T    [2048 x 512 x 512]  NT
    mma_gemm<<<dim3(4, 16, 1), T>>>(slots, slots_enc, Dn, Wq, nullptr, Dn, 0, nullptr,
        pq, Dn, Bn*Qn, Dn, Dn, 1.f, 1, 0, 0, 0, 0, 0, 0);

    // qk[b,h,q,:] = (q_head/8) @ Wk_head   [128 x 512 x 64]  NN, batched (b,h)
    mma_gemm<<<dim3(4, 1, Bn*Hn), T>>>(pq, nullptr, Dn, Wk, nullptr, Dn, 1, nullptr,
        pqk, Dn, Qn, Dn, Cn, 0.125f, Hn,
        (long long)Qn*Dn, 64,
        0, (long long)Cn*Dn,
        (long long)Hn*Qn*Dn, (long long)Qn*Dn);

    // dots[b,h,q,k] = qk @ (ctx + ctx_enc)^T   [128 x 4096 x 512]  NT, batched (b,h)
    mma_gemm<<<dim3(Kn/128, 1, Bn*Hn), T>>>(pqk, nullptr, Dn, ctx, ctx_enc, Dn, 0, nullptr,
        pdots, Kn, Qn, Kn, Dn, 1.f, Hn,
        (long long)Hn*Qn*Dn, (long long)Qn*Dn,
        (long long)Kn*Dn, 0,
        (long long)Hn*Qn*Kn, (long long)Qn*Kn);

    score_kernel  <<<dim3(Kn/128, Hn, Bn), 128>>>();
    topk_kernel   <<<Bn, 128>>>();
    softmax_kernel<<<dim3(Kn/128, Hn, Bn), 128>>>();

    // S1f = attn_un @ ctx, S1e = attn_un @ ctx_enc   [264 x 512 x 4096]  NN, batched b
    mma_gemm<<<dim3(4, 3, Bn), T>>>(pattn, nullptr, Kn, ctx, nullptr, Dn, 1, nullptr,
        ps1f, Dn, Hn*KEEPN, Dn, Kn, 1.f, 1,
        (long long)Hn*KEEPN*Kn, 0, (long long)Kn*Dn, 0,
        (long long)Hn*KEEPN*Dn, 0);
    mma_gemm<<<dim3(4, 3, Bn), T>>>(pattn, nullptr, Kn, ctx_enc, nullptr, Dn, 1, nullptr,
        ps1e, Dn, Hn*KEEPN, Dn, Kn, 1.f, 1,
        (long long)Hn*KEEPN*Kn, 0, (long long)Kn*Dn, 0,
        (long long)Hn*KEEPN*Dn, 0);

    normalize_kernel<<<(Bn*Hn*KEEPN*Dn + 255)/256, 256>>>();

    // per-head contraction:  pref[b,j,h*64+c] = S1n[b,h,j,:] . Wf[h*64+c,:]   NT batched (b,h)
    mma_gemm<<<dim3(1, 1, Bn*Hn), T>>>(ps1f, nullptr, Dn, Wf, nullptr, Dn, 0, nullptr,
        ppref, Dn, KEEPN, Cn, Dn, 1.f, Hn,
        (long long)Hn*KEEPN*Dn, (long long)KEEPN*Dn,
        0, (long long)Cn*Dn,
        (long long)KEEPN*Dn, (long long)Cn);
    mma_gemm<<<dim3(1, 1, Bn*Hn), T>>>(ps1e, nullptr, Dn, We, nullptr, Dn, 0, nullptr,
        ppree, Dn, KEEPN, Cn, Dn, 1.f, Hn,
        (long long)Hn*KEEPN*Dn, (long long)KEEPN*Dn,
        0, (long long)Cn*Dn,
        (long long)KEEPN*Dn, (long long)Cn);

    // output projections straight into d_out  [528 x 512 x 512]  NT
    mma_gemm<<<dim3(4, 5, 1), T>>>(ppref, nullptr, Dn, Wof, nullptr, Dn, 0, bof,
        outp, Dn, Bn*KEEPN, Dn, Dn, 1.f, 1, 0, 0, 0, 0, 0, 0);
    mma_gemm<<<dim3(4, 5, 1), T>>>(ppree, nullptr, Dn, Woe, nullptr, Dn, 0, boe,
        outp + (size_t)Bn*KEEPN*Dn, Dn, Bn*KEEPN, Dn, Dn, 1.f, 1, 0, 0, 0, 0, 0, 0);

    finalize_keep_kernel<<<3, 256>>>(outp + 2*(size_t)Bn*KEEPN*Dn);
}

// round 3
// speedup vs baseline: 2.1636x; 1.6711x over previous
#include <cuda_runtime.h>
#include <cuda_bf16.h>
#include <math.h>
#include <stdint.h>

#define Bn 16
#define Qn 128
#define Kn 4096
#define Dn 512
#define Hn 8
#define Cn 64
#define MQn 32
#define KEEPN 33   // MQ + 1

// ---------------- scratch (device globals; no allocation allowed) ----------------
static __device__ float g_q   [(size_t)Bn*Qn*Dn];            //   4 MB q projections [B,Q,D]
static __device__ float g_k   [(size_t)Bn*Kn*Dn];            // 134 MB k projections [B,K,D]
static __device__ float g_dots[(size_t)Bn*Hn*Qn*Kn];         // 256 MB [B,H,Q,K]
static __device__ float g_attn[(size_t)Bn*Hn*KEEPN*Kn];      //  66 MB unnormalized attn
static __device__ float g_score[Bn*(Qn-1)];
static __device__ int   g_keep [Bn*KEEPN];
static __device__ float g_rowsum[Bn*Hn*KEEPN];
static __device__ float g_s1f [(size_t)Bn*Hn*KEEPN*Dn];
static __device__ float g_s1e [(size_t)Bn*Hn*KEEPN*Dn];
static __device__ float g_pref[(size_t)Bn*KEEPN*Dn];
static __device__ float g_pree[(size_t)Bn*KEEPN*Dn];

// ---------------- 3-term bf16-split tensor-core GEMM ----------------
// C[r,c] = scale * sum_k Aeff[r,k] * Beff[k,c]  (+ bias[c])
//   Aeff = A1 (+A2), row-major lda.
//   transB=0 (NT): Beff[k,c] = W1[c*ldw + k] (+W2)
//   transB=1 (NN): Beff[k,c] = W1[k*ldw + c] (+W2)
// Inputs split a = a_hi + a_lo (bf16 each) at SMEM-load time; inner loop does
// 3 HMMA.16816 products (hh, lh, hl) -> ~1e-5 per-product accuracy.

#define BM 128
#define BN 128
#define BKt 16          // k per mainloop tile (one m16n8k16 slab)
#define LDT 136         // padded row length (conflict-free fragment loads)

__device__ __forceinline__ void pack_split(float x, float y, uint32_t& h, uint32_t& l) {
    __nv_bfloat162 ph = __floats2bfloat162_rn(x, y);
    float rx = x - __bfloat162float(ph.x);
    float ry = y - __bfloat162float(ph.y);
    __nv_bfloat162 pl = __floats2bfloat162_rn(rx, ry);
    h = *reinterpret_cast<uint32_t*>(&ph);
    l = *reinterpret_cast<uint32_t*>(&pl);
}

__device__ __forceinline__ void mma16(float* d, const uint32_t* a, const uint32_t* b) {
    asm volatile(
        "mma.sync.aligned.m16n8k16.row.col.f32.bf16.bf16.f32 "
        "{%0,%1,%2,%3}, {%4,%5,%6,%7}, {%8,%9}, {%0,%1,%2,%3};"
        : "+f"(d[0]), "+f"(d[1]), "+f"(d[2]), "+f"(d[3])
        : "r"(a[0]), "r"(a[1]), "r"(a[2]), "r"(a[3]), "r"(b[0]), "r"(b[1]));
}

__global__ void __launch_bounds__(256, 2) mma_gemm(
    const float* __restrict__ A1, const float* __restrict__ A2, int lda,
    const float* __restrict__ W1, const float* __restrict__ W2, int ldw, int transB,
    const float* __restrict__ bias,
    float* __restrict__ C, int ldc,
    int nrows, int ncols, int kdim, float scale, int zdiv,
    long long sAb, long long sAh, long long sWb, long long sWh,
    long long sCb, long long sCh)
{
    // packed bf16x2 planes, fragment-order [packed_k][row/col]
    __shared__ __align__(16) uint32_t Ah[BKt/2][LDT], Al[BKt/2][LDT];
    __shared__ __align__(16) uint32_t Bh[BKt/2][LDT], Bl[BKt/2][LDT];

    int z = blockIdx.z;
    int b = z / zdiv, h = z - b * zdiv;
    A1 += (long long)b * sAb + (long long)h * sAh;
    if (A2) A2 += (long long)b * sAb + (long long)h * sAh;
    W1 += (long long)b * sWb + (long long)h * sWh;
    if (W2) W2 += (long long)b * sWb + (long long)h * sWh;
    C  += (long long)b * sCb + (long long)h * sCh;

    const int tid  = threadIdx.x;
    const int lane = tid & 31;
    const int warp = tid >> 5;
    const int wr = warp >> 2;        // 0..1  (64-row warp tile)
    const int wc = warp & 3;         // 0..3  (32-col warp tile)
    const int g  = lane >> 2;        // 0..7
    const int t  = lane & 3;         // 0..3
    const int row0 = blockIdx.y * BM;
    const int col0 = blockIdx.x * BN;

    float acc[4][4][4];
    #pragma unroll
    for (int mi = 0; mi < 4; mi++)
        #pragma unroll
        for (int ni = 0; ni < 4; ni++)
            #pragma unroll
            for (int j = 0; j < 4; j++) acc[mi][ni][j] = 0.f;

    for (int k0 = 0; k0 < kdim; k0 += BKt) {
        // ---- A tile: 128 rows x 16 k  (512 float4 loads, 2 rounds of 256 thr)
        #pragma unroll
        for (int it = 0; it < 2; it++) {
            int i = it * 256 + tid;
            int r = i >> 2, kc = (i & 3) * 4;       // kc in {0,4,8,12}
            float4 v = make_float4(0.f, 0.f, 0.f, 0.f);
            if (row0 + r < nrows) {
                v = *(const float4*)(A1 + (long long)(row0 + r) * lda + k0 + kc);
                if (A2) {
                    float4 v2 = *(const float4*)(A2 + (long long)(row0 + r) * lda + k0 + kc);
                    v.x += v2.x; v.y += v2.y; v.z += v2.z; v.w += v2.w;
                }
            }
            int kk = kc >> 1;                        // packed-k index {0,2,4,6}
            uint32_t h0, l0, h1, l1;
            pack_split(v.x, v.y, h0, l0);
            pack_split(v.z, v.w, h1, l1);
            Ah[kk][r] = h0;   Al[kk][r] = l0;
            Ah[kk+1][r] = h1; Al[kk+1][r] = l1;
        }
        // ---- B tile -> packed [k/2][col]
        if (!transB) {   // NT: rows of W are output cols, k contiguous
            #pragma unroll
            for (int it = 0; it < 2; it++) {
                int i = it * 256 + tid;
                int r = i >> 2, kc = (i & 3) * 4;
                float4 v = make_float4(0.f, 0.f, 0.f, 0.f);
                if (col0 + r < ncols) {
                    v = *(const float4*)(W1 + (long long)(col0 + r) * ldw + k0 + kc);
                    if (W2) {
                        float4 v2 = *(const float4*)(W2 + (long long)(col0 + r) * ldw + k0 + kc);
                        v.x += v2.x; v.y += v2.y; v.z += v2.z; v.w += v2.w;
                    }
                }
                int kk = kc >> 1;
                uint32_t h0, l0, h1, l1;
                pack_split(v.x, v.y, h0, l0);
                pack_split(v.z, v.w, h1, l1);
                Bh[kk][r] = h0;   Bl[kk][r] = l0;
                Bh[kk+1][r] = h1; Bl[kk+1][r] = l1;
            }
        } else {         // NN: k is the row dim; pack pairs of k rows per column
            int kr = tid >> 5;            // packed-k 0..7
            int n4 = (tid & 31) * 4;      // column group
            float4 va = make_float4(0.f,0.f,0.f,0.f), vb = va;
            if (col0 + n4 + 3 < ncols) {
                va = *(const float4*)(W1 + (long long)(k0 + 2*kr)     * ldw + col0 + n4);
                vb = *(const float4*)(W1 + (long long)(k0 + 2*kr + 1) * ldw + col0 + n4);
                if (W2) {
                    float4 wa = *(const float4*)(W2 + (long long)(k0 + 2*kr)     * ldw + col0 + n4);
                    float4 wb = *(const float4*)(W2 + (long long)(k0 + 2*kr + 1) * ldw + col0 + n4);
                    va.x+=wa.x; va.y+=wa.y; va.z+=wa.z; va.w+=wa.w;
                    vb.x+=wb.x; vb.y+=wb.y; vb.z+=wb.z; vb.w+=wb.w;
                }
            }
            uint32_t hh, ll;
            pack_split(va.x, vb.x, hh, ll); Bh[kr][n4+0] = hh; Bl[kr][n4+0] = ll;
            pack_split(va.y, vb.y, hh, ll); Bh[kr][n4+1] = hh; Bl[kr][n4+1] = ll;
            pack_split(va.z, vb.z, hh, ll); Bh[kr][n4+2] = hh; Bl[kr][n4+2] = ll;
            pack_split(va.w, vb.w, hh, ll); Bh[kr][n4+3] = hh; Bl[kr][n4+3] = ll;
        }
        __syncthreads();

        // ---- one m16n8k16 slab per tile
        uint32_t bh[4][2], bl[4][2];
        #pragma unroll
        for (int ni = 0; ni < 4; ni++) {
            int c = wc * 32 + ni * 8 + g;
            bh[ni][0] = Bh[t][c];   bh[ni][1] = Bh[t+4][c];
            bl[ni][0] = Bl[t][c];   bl[ni][1] = Bl[t+4][c];
        }
        #pragma unroll
        for (int mi = 0; mi < 4; mi++) {
            int r = wr * 64 + mi * 16 + g;
            uint32_t ah[4], al[4];
            ah[0] = Ah[t][r];     ah[1] = Ah[t][r+8];
            ah[2] = Ah[t+4][r];   ah[3] = Ah[t+4][r+8];
            al[0] = Al[t][r];     al[1] = Al[t][r+8];
            al[2] = Al[t+4][r];   al[3] = Al[t+4][r+8];
            #pragma unroll
            for (int ni = 0; ni < 4; ni++) {
                mma16(acc[mi][ni], ah, bh[ni]);
                mma16(acc[mi][ni], al, bh[ni]);
                mma16(acc[mi][ni], ah, bl[ni]);
            }
        }
        __syncthreads();
    }

    // ---- epilogue
    #pragma unroll
    for (int mi = 0; mi < 4; mi++) {
        #pragma unroll
        for (int ni = 0; ni < 4; ni++) {
            int r = row0 + wr * 64 + mi * 16 + g;
            int c = col0 + wc * 32 + ni * 8 + 2 * t;
            #pragma unroll
            for (int j = 0; j < 4; j++) {
                int rr = r + (j >> 1) * 8;
                int cc = c + (j & 1);
                if (rr < nrows && cc < ncols) {
                    float v = acc[mi][ni][j] * scale;
                    if (bias) v += bias[cc];
                    C[(long long)rr * ldc + cc] = v;
                }
            }
        }
    }
}

// ---------------- per-launch state reset ----------------
__global__ void init_kernel() {
    for (int i = threadIdx.x; i < Bn*(Qn-1); i += 256) g_score[i] = 0.f;
    for (int i = threadIdx.x; i < Bn*Hn*KEEPN; i += 256) g_rowsum[i] = 0.f;
}

// ---------------- query scoring ----------------
__global__ void score_kernel() {
    int b = blockIdx.z, h = blockIdx.y;
    int k = blockIdx.x * 128 + threadIdx.x;
    const float* col = g_dots + ((size_t)((b*Hn + h) * Qn)) * Kn + k;
    float s = 0.f;
    #pragma unroll 4
    for (int q = 1; q < Qn; q++) s += __expf(col[(size_t)q * Kn]);
    float inv = 1.f / s;
    __shared__ float wm[4][Qn];
    int lane = threadIdx.x & 31, wid = threadIdx.x >> 5;
    for (int q = 1; q < Qn; q++) {
        float v = __expf(col[(size_t)q * Kn]) * inv;
        #pragma unroll
        for (int o = 16; o > 0; o >>= 1)
            v = fmaxf(v, __shfl_xor_sync(0xffffffffu, v, o));
        if (lane == 0) wm[wid][q] = v;
    }
    __syncthreads();
    int q = threadIdx.x;
    if (q >= 1 && q < Qn) {
        float m = fmaxf(fmaxf(wm[0][q], wm[1][q]), fmaxf(wm[2][q], wm[3][q]));
        atomicMax((int*)&g_score[b*(Qn-1) + q - 1], __float_as_int(m)); // scores > 0
    }
}

// ---------------- top-32 selection (ties -> lower index) ----------------
__global__ void topk_kernel() {
    int b = blockIdx.x;
    int t = threadIdx.x;   // 128
    __shared__ float sv[128];
    __shared__ float rv[128];
    __shared__ int   ri[128];
    sv[t] = (t < Qn-1) ? g_score[b*(Qn-1) + t] : -INFINITY;
    __syncthreads();
    for (int r = 0; r < MQn; r++) {
        rv[t] = sv[t]; ri[t] = t;
        __syncthreads();
        for (int off = 64; off > 0; off >>= 1) {
            if (t < off) {
                float v2 = rv[t+off]; int i2 = ri[t+off];
                if (v2 > rv[t] || (v2 == rv[t] && i2 < ri[t])) { rv[t] = v2; ri[t] = i2; }
            }
            __syncthreads();
        }
        int win = ri[0];
        if (t == 0) g_keep[b*KEEPN + 1 + r] = win + 1;
        if (t == win) sv[t] = -INFINITY;
        __syncthreads();
    }
    if (t == 0) g_keep[b*KEEPN] = 0;
}

// ---------------- gather + competitive softmax (query axis), rowsums ----------------
__global__ void softmax_kernel() {
    int b = blockIdx.z, h = blockIdx.y;
    int k = blockIdx.x * 128 + threadIdx.x;
    __shared__ int   kq[KEEPN];
    __shared__ float rs[KEEPN];
    if (threadIdx.x < KEEPN) {
        kq[threadIdx.x] = g_keep[b*KEEPN + threadIdx.x];
        rs[threadIdx.x] = 0.f;
    }
    __syncthreads();
    const float* base = g_dots + ((size_t)((b*Hn + h) * Qn)) * Kn + k;
    float d[KEEPN];
    float m = -INFINITY;
    #pragma unroll
    for (int j = 0; j < KEEPN; j++) {
        d[j] = base[(size_t)kq[j] * Kn];
        m = fmaxf(m, d[j]);
    }
    float s = 0.f;
    #pragma unroll
    for (int j = 0; j < KEEPN; j++) { d[j] = __expf(d[j] - m); s += d[j]; }
    float inv = 1.f / s;
    float* outp = g_attn + ((size_t)((b*Hn + h) * KEEPN)) * Kn + k;
    int lane = threadIdx.x & 31;
    #pragma unroll
    for (int j = 0; j < KEEPN; j++) {
        float a = d[j] * inv;
        outp[(size_t)j * Kn] = a;
        float w = a;
        #pragma unroll
        for (int o = 16; o > 0; o >>= 1) w += __shfl_xor_sync(0xffffffffu, w, o);
        if (lane == 0) atomicAdd(&rs[j], w);
    }
    __syncthreads();
    if (threadIdx.x < KEEPN)
        atomicAdd(&g_rowsum[(b*Hn + h)*KEEPN + threadIdx.x], rs[threadIdx.x]);
}

// ---------------- key-axis renormalization of S1 ----------------
__global__ void normalize_kernel() {
    int idx = blockIdx.x * 256 + threadIdx.x;
    const int total = Bn*Hn*KEEPN*Dn;
    if (idx >= total) return;
    int r = idx / Dn;
    float inv = 1.f / (g_rowsum[r] + 1e-8f);
    g_s1f[idx] *= inv;
    g_s1e[idx] *= inv;
}

__global__ void finalize_keep_kernel(float* outp) {
    int i = blockIdx.x * 256 + threadIdx.x;
    if (i < Bn*KEEPN) outp[i] = (float)g_keep[i];
}

// ---------------- launch ----------------
extern "C" void kernel_launch(void* const* d_in, const int* in_sizes, int n_in,
                              void* d_out, int out_size) {
    const float* slots     = (const float*)d_in[0];
    const float* slots_enc = (const float*)d_in[1];
    const float* ctx       = (const float*)d_in[2];
    const float* ctx_enc   = (const float*)d_in[3];
    const float* Wq  = (const float*)d_in[4];
    const float* Wk  = (const float*)d_in[5];
    const float* Wf  = (const float*)d_in[6];
    const float* We  = (const float*)d_in[7];
    const float* Wof = (const float*)d_in[8];
    const float* bof = (const float*)d_in[9];
    const float* Woe = (const float*)d_in[10];
    const float* boe = (const float*)d_in[11];
    float* outp = (float*)d_out;

    float *pq, *pk, *pdots, *pattn, *ps1f, *ps1e, *ppref, *ppree;
    cudaGetSymbolAddress((void**)&pq,    g_q);
    cudaGetSymbolAddress((void**)&pk,    g_k);
    cudaGetSymbolAddress((void**)&pdots, g_dots);
    cudaGetSymbolAddress((void**)&pattn, g_attn);
    cudaGetSymbolAddress((void**)&ps1f,  g_s1f);
    cudaGetSymbolAddress((void**)&ps1e,  g_s1e);
    cudaGetSymbolAddress((void**)&ppref, g_pref);
    cudaGetSymbolAddress((void**)&ppree, g_pree);

    dim3 T(256);

    init_kernel<<<1, 256>>>();

    // q = (slots + slots_enc) @ Wq^T    [2048 x 512 x 512]  NT
    mma_gemm<<<dim3(4, 16, 1), T>>>(slots, slots_enc, Dn, Wq, nullptr, Dn, 0, nullptr,
        pq, Dn, Bn*Qn, Dn, Dn, 1.f, 1, 0, 0, 0, 0, 0, 0);

    // k = (ctx + ctx_enc) @ Wk^T        [65536 x 512 x 512]  NT
    mma_gemm<<<dim3(4, 512, 1), T>>>(ctx, ctx_enc, Dn, Wk, nullptr, Dn, 0, nullptr,
        pk, Dn, Bn*Kn, Dn, Dn, 1.f, 1, 0, 0, 0, 0, 0, 0);

    // dots[b,h,q,k] = (q_h/8) . k_h     [128 x 4096 x 64]  NT, batched (b,h)
    mma_gemm<<<dim3(Kn/128, 1, Bn*Hn), T>>>(pq, nullptr, Dn, pk, nullptr, Dn, 0, nullptr,
        pdots, Kn, Qn, Kn, Cn, 0.125f, Hn,
        (long long)Qn*Dn, 64,
        (long long)Kn*Dn, 64,
        (long long)Hn*Qn*Kn, (long long)Qn*Kn);

    score_kernel  <<<dim3(Kn/128, Hn, Bn), 128>>>();
    topk_kernel   <<<Bn, 128>>>();
    softmax_kernel<<<dim3(Kn/128, Hn, Bn), 128>>>();

    // S1f = attn_un @ ctx, S1e = attn_un @ ctx_enc   [264 x 512 x 4096]  NN, batched b
    mma_gemm<<<dim3(4, 3, Bn), T>>>(pattn, nullptr, Kn, ctx, nullptr, Dn, 1, nullptr,
        ps1f, Dn, Hn*KEEPN, Dn, Kn, 1.f, 1,
        (long long)Hn*KEEPN*Kn, 0, (long long)Kn*Dn, 0,
        (long long)Hn*KEEPN*Dn, 0);
    mma_gemm<<<dim3(4, 3, Bn), T>>>(pattn, nullptr, Kn, ctx_enc, nullptr, Dn, 1, nullptr,
        ps1e, Dn, Hn*KEEPN, Dn, Kn, 1.f, 1,
        (long long)Hn*KEEPN*Kn, 0, (long long)Kn*Dn, 0,
        (long long)Hn*KEEPN*Dn, 0);

    normalize_kernel<<<(Bn*Hn*KEEPN*Dn + 255)/256, 256>>>();

    // per-head contraction:  pref[b,j,h*64+c] = S1n[b,h,j,:] . Wf[h*64+c,:]   NT batched (b,h)
    mma_gemm<<<dim3(1, 1, Bn*Hn), T>>>(ps1f, nullptr, Dn, Wf, nullptr, Dn, 0, nullptr,
        ppref, Dn, KEEPN, Cn, Dn, 1.f, Hn,
        (long long)Hn*KEEPN*Dn, (long long)KEEPN*Dn,
        0, (long long)Cn*Dn,
        (long long)KEEPN*Dn, (long long)Cn);
    mma_gemm<<<dim3(1, 1, Bn*Hn), T>>>(ps1e, nullptr, Dn, We, nullptr, Dn, 0, nullptr,
        ppree, Dn, KEEPN, Cn, Dn, 1.f, Hn,
        (long long)Hn*KEEPN*Dn, (long long)KEEPN*Dn,
        0, (long long)Cn*Dn,
        (long long)KEEPN*Dn, (long long)Cn);

    // output projections straight into d_out  [528 x 512 x 512]  NT
    mma_gemm<<<dim3(4, 5, 1), T>>>(ppref, nullptr, Dn, Wof, nullptr, Dn, 0, bof,
        outp, Dn, Bn*KEEPN, Dn, Dn, 1.f, 1, 0, 0, 0, 0, 0, 0);
    mma_gemm<<<dim3(4, 5, 1), T>>>(ppree, nullptr, Dn, Woe, nullptr, Dn, 0, boe,
        outp + (size_t)Bn*KEEPN*Dn, Dn, Bn*KEEPN, Dn, Dn, 1.f, 1, 0, 0, 0, 0, 0, 0);

    finalize_keep_kernel<<<3, 256>>>(outp + 2*(size_t)Bn*KEEPN*Dn);
}

// round 4
// speedup vs baseline: 2.6605x; 1.2297x over previous
#include <cuda_runtime.h>
#include <cuda_bf16.h>
#include <math.h>
#include <stdint.h>

#define Bn 16
#define Qn 128
#define Kn 4096
#define Dn 512
#define Hn 8
#define Cn 64
#define MQn 32
#define KEEPN 33   // MQ + 1

// ---------------- scratch (device globals; no allocation allowed) ----------------
static __device__ float g_q   [(size_t)Bn*Qn*Dn];            //   4 MB q projections [B,Q,D]
static __device__ float g_k   [(size_t)Bn*Kn*Dn];            // 134 MB k projections [B,K,D]
static __device__ float g_dots[(size_t)Bn*Hn*Qn*Kn];         // 256 MB [B,H,Q,K]
static __device__ float g_attn[(size_t)Bn*Hn*KEEPN*Kn];      //  66 MB unnormalized attn
static __device__ float g_score[Bn*(Qn-1)];
static __device__ int   g_keep [Bn*KEEPN];
static __device__ float g_rowsum[Bn*Hn*KEEPN];
static __device__ float g_s1f [(size_t)Bn*Hn*KEEPN*Dn];
static __device__ float g_s1e [(size_t)Bn*Hn*KEEPN*Dn];
static __device__ float g_pref[(size_t)Bn*KEEPN*Dn];
static __device__ float g_pree[(size_t)Bn*KEEPN*Dn];

// ---------------- 3-term bf16-split tensor-core GEMM (double-buffered) ----------------
// C[r,c] = scale * sum_k Aeff[r,k] * Beff[k,c]  (+ bias[c])
//   transB=0 (NT): Beff[k,c] = W1[c*ldw + k] (+W2)
//   transB=1 (NN): Beff[k,c] = W1[k*ldw + c] (+W2)
// Pairing: if blockIdx.z >= zpair, switch to (A1b, W1b, biasb, C+sCpair), z -= zpair.
// doScore: fused CompetitiveSoftmax query-scoring epilogue (dots GEMM only).

#define BM 128
#define BN 128
#define BKt 16
#define KK  8          // BKt/2 packed-k rows
#define LDT 136        // padded row (conflict-free fragment loads)

__device__ __forceinline__ void pack_split(float x, float y, uint32_t& h, uint32_t& l) {
    __nv_bfloat162 ph = __floats2bfloat162_rn(x, y);
    float rx = x - __bfloat162float(ph.x);
    float ry = y - __bfloat162float(ph.y);
    __nv_bfloat162 pl = __floats2bfloat162_rn(rx, ry);
    h = *reinterpret_cast<uint32_t*>(&ph);
    l = *reinterpret_cast<uint32_t*>(&pl);
}

__device__ __forceinline__ void mma16(float* d, const uint32_t* a, const uint32_t* b) {
    asm volatile(
        "mma.sync.aligned.m16n8k16.row.col.f32.bf16.bf16.f32 "
        "{%0,%1,%2,%3}, {%4,%5,%6,%7}, {%8,%9}, {%0,%1,%2,%3};"
        : "+f"(d[0]), "+f"(d[1]), "+f"(d[2]), "+f"(d[3])
        : "r"(a[0]), "r"(a[1]), "r"(a[2]), "r"(a[3]), "r"(b[0]), "r"(b[1]));
}

__global__ void __launch_bounds__(256, 2) mma_gemm(
    const float* __restrict__ A1, const float* __restrict__ A2,
    const float* __restrict__ A1b, int lda,
    const float* __restrict__ W1, const float* __restrict__ W2,
    const float* __restrict__ W1b, int ldw, int transB,
    const float* __restrict__ bias, const float* __restrict__ biasb,
    float* __restrict__ C, long long sCpair, int ldc,
    int nrows, int ncols, int kdim, float scale, int zdiv, int zpair,
    long long sAb, long long sAh, long long sWb, long long sWh,
    long long sCb, long long sCh, int doScore)
{
    __shared__ __align__(16) uint32_t sAh_[2][KK][LDT], sAl_[2][KK][LDT];
    __shared__ __align__(16) uint32_t sBh_[2][KK][LDT], sBl_[2][KK][LDT];
    __shared__ float scoreBuf[BN + BM];

    int z = blockIdx.z;
    if (z >= zpair) {
        z -= zpair;
        if (A1b) A1 = A1b;
        if (W1b) W1 = W1b;
        bias = biasb;
        C += sCpair;
    }
    int b = z / zdiv, h = z - b * zdiv;
    A1 += (long long)b * sAb + (long long)h * sAh;
    if (A2) A2 += (long long)b * sAb + (long long)h * sAh;
    W1 += (long long)b * sWb + (long long)h * sWh;
    if (W2) W2 += (long long)b * sWb + (long long)h * sWh;
    C  += (long long)b * sCb + (long long)h * sCh;

    const int tid  = threadIdx.x;
    const int lane = tid & 31;
    const int warp = tid >> 5;
    const int wr = warp >> 2;        // 0..1
    const int wc = warp & 3;         // 0..3
    const int g  = lane >> 2;        // 0..7
    const int t  = lane & 3;         // 0..3
    const int row0 = blockIdx.y * BM;
    const int col0 = blockIdx.x * BN;

    float acc[4][4][4];
    #pragma unroll
    for (int mi = 0; mi < 4; mi++)
        #pragma unroll
        for (int ni = 0; ni < 4; ni++)
            #pragma unroll
            for (int j = 0; j < 4; j++) acc[mi][ni][j] = 0.f;

    float4 rA[2], rB[2];

    auto ldA = [&](int k0) {
        #pragma unroll
        for (int it = 0; it < 2; it++) {
            int i = it * 256 + tid;
            int r = i >> 2, kc = (i & 3) * 4;
            float4 v = make_float4(0.f, 0.f, 0.f, 0.f);
            if (row0 + r < nrows) {
                v = *(const float4*)(A1 + (long long)(row0 + r) * lda + k0 + kc);
                if (A2) {
                    float4 u = *(const float4*)(A2 + (long long)(row0 + r) * lda + k0 + kc);
                    v.x += u.x; v.y += u.y; v.z += u.z; v.w += u.w;
                }
            }
            rA[it] = v;
        }
    };
    auto ldB = [&](int k0) {
        if (!transB) {
            #pragma unroll
            for (int it = 0; it < 2; it++) {
                int i = it * 256 + tid;
                int r = i >> 2, kc = (i & 3) * 4;
                float4 v = make_float4(0.f, 0.f, 0.f, 0.f);
                if (col0 + r < ncols) {
                    v = *(const float4*)(W1 + (long long)(col0 + r) * ldw + k0 + kc);
                    if (W2) {
                        float4 u = *(const float4*)(W2 + (long long)(col0 + r) * ldw + k0 + kc);
                        v.x += u.x; v.y += u.y; v.z += u.z; v.w += u.w;
                    }
                }
                rB[it] = v;
            }
        } else {
            int kr = tid >> 5, n4 = (tid & 31) * 4;
            float4 va = make_float4(0.f,0.f,0.f,0.f), vb = va;
            if (col0 + n4 + 3 < ncols) {
                va = *(const float4*)(W1 + (long long)(k0 + 2*kr)     * ldw + col0 + n4);
                vb = *(const float4*)(W1 + (long long)(k0 + 2*kr + 1) * ldw + col0 + n4);
                if (W2) {
                    float4 wa = *(const float4*)(W2 + (long long)(k0 + 2*kr)     * ldw + col0 + n4);
                    float4 wb = *(const float4*)(W2 + (long long)(k0 + 2*kr + 1) * ldw + col0 + n4);
                    va.x+=wa.x; va.y+=wa.y; va.z+=wa.z; va.w+=wa.w;
                    vb.x+=wb.x; vb.y+=wb.y; vb.z+=wb.z; vb.w+=wb.w;
                }
            }
            rB[0] = va; rB[1] = vb;
        }
    };
    auto stAB = [&](int s) {
        #pragma unroll
        for (int it = 0; it < 2; it++) {
            int i = it * 256 + tid;
            int r = i >> 2, kc = (i & 3) * 4, kk = kc >> 1;
            uint32_t h0, l0, h1, l1;
            pack_split(rA[it].x, rA[it].y, h0, l0);
            pack_split(rA[it].z, rA[it].w, h1, l1);
            sAh_[s][kk][r]   = h0; sAl_[s][kk][r]   = l0;
            sAh_[s][kk+1][r] = h1; sAl_[s][kk+1][r] = l1;
        }
        if (!transB) {
            #pragma unroll
            for (int it = 0; it < 2; it++) {
                int i = it * 256 + tid;
                int r = i >> 2, kc = (i & 3) * 4, kk = kc >> 1;
                uint32_t h0, l0, h1, l1;
                pack_split(rB[it].x, rB[it].y, h0, l0);
                pack_split(rB[it].z, rB[it].w, h1, l1);
                sBh_[s][kk][r]   = h0; sBl_[s][kk][r]   = l0;
                sBh_[s][kk+1][r] = h1; sBl_[s][kk+1][r] = l1;
            }
        } else {
            int kr = tid >> 5, n4 = (tid & 31) * 4;
            uint32_t hv[4], lv[4];
            pack_split(rB[0].x, rB[1].x, hv[0], lv[0]);
            pack_split(rB[0].y, rB[1].y, hv[1], lv[1]);
            pack_split(rB[0].z, rB[1].z, hv[2], lv[2]);
            pack_split(rB[0].w, rB[1].w, hv[3], lv[3]);
            *(uint4*)&sBh_[s][kr][n4] = *(uint4*)hv;
            *(uint4*)&sBl_[s][kr][n4] = *(uint4*)lv;
        }
    };
    auto mmaStep = [&](int s) {
        uint32_t bh[4][2], bl[4][2];
        #pragma unroll
        for (int ni = 0; ni < 4; ni++) {
            int c = wc * 32 + ni * 8 + g;
            bh[ni][0] = sBh_[s][t][c];   bh[ni][1] = sBh_[s][t+4][c];
            bl[ni][0] = sBl_[s][t][c];   bl[ni][1] = sBl_[s][t+4][c];
        }
        #pragma unroll
        for (int mi = 0; mi < 4; mi++) {
            int r = wr * 64 + mi * 16 + g;
            uint32_t ah[4], al[4];
            ah[0] = sAh_[s][t][r];     ah[1] = sAh_[s][t][r+8];
            ah[2] = sAh_[s][t+4][r];   ah[3] = sAh_[s][t+4][r+8];
            al[0] = sAl_[s][t][r];     al[1] = sAl_[s][t][r+8];
            al[2] = sAl_[s][t+4][r];   al[3] = sAl_[s][t+4][r+8];
            #pragma unroll
            for (int ni = 0; ni < 4; ni++) {
                mma16(acc[mi][ni], ah, bh[ni]);
                mma16(acc[mi][ni], al, bh[ni]);
                mma16(acc[mi][ni], ah, bl[ni]);
            }
        }
    };

    const int nt = kdim / BKt;
    ldA(0); ldB(0);
    stAB(0);
    __syncthreads();
    for (int it = 0; it < nt; it++) {
        int cur = it & 1;
        if (it + 1 < nt) { ldA((it + 1) * BKt); ldB((it + 1) * BKt); }
        mmaStep(cur);
        if (it + 1 < nt) {
            stAB(cur ^ 1);
            __syncthreads();
        }
    }

    // ---- C epilogue
    #pragma unroll
    for (int mi = 0; mi < 4; mi++) {
        #pragma unroll
        for (int ni = 0; ni < 4; ni++) {
            int r = row0 + wr * 64 + mi * 16 + g;
            int c = col0 + wc * 32 + ni * 8 + 2 * t;
            #pragma unroll
            for (int j = 0; j < 4; j++) {
                int rr = r + (j >> 1) * 8;
                int cc = c + (j & 1);
                if (rr < nrows && cc < ncols) {
                    float v = acc[mi][ni][j] * scale;
                    if (bias) v += bias[cc];
                    C[(long long)rr * ldc + cc] = v;
                }
            }
        }
    }

    // ---- fused query-scoring epilogue (dots only): column softmax over q=1..127,
    //      per-q max over this 128-key tile, atomicMax into g_score[b].
    if (doScore) {
        float* colsum = scoreBuf;         // [BN]
        float* rowmax = scoreBuf + BN;    // [BM]
        for (int i = tid; i < BN + BM; i += 256) scoreBuf[i] = 0.f;
        __syncthreads();

        // pass 1: per-thread column partial sums over its 8 rows
        float cs[8];
        #pragma unroll
        for (int q = 0; q < 8; q++) cs[q] = 0.f;
        #pragma unroll
        for (int mi = 0; mi < 4; mi++)
            #pragma unroll
            for (int ni = 0; ni < 4; ni++)
                #pragma unroll
                for (int j = 0; j < 4; j++) {
                    int grow = wr * 64 + mi * 16 + g + 8 * (j >> 1);
                    if (grow != 0)
                        cs[ni * 2 + (j & 1)] += __expf(acc[mi][ni][j] * scale);
                }
        #pragma unroll
        for (int o = 4; o <= 16; o <<= 1)
            #pragma unroll
            for (int q = 0; q < 8; q++)
                cs[q] += __shfl_xor_sync(0xffffffffu, cs[q], o);
        if (g == 0) {
            #pragma unroll
            for (int q = 0; q < 8; q++)
                atomicAdd(&colsum[wc * 32 + (q >> 1) * 8 + 2 * t + (q & 1)], cs[q]);
        }
        __syncthreads();

        // pass 2: per-thread row max of e/colsum over its 8 cols
        float rm[8];
        #pragma unroll
        for (int q = 0; q < 8; q++) rm[q] = 0.f;
        #pragma unroll
        for (int mi = 0; mi < 4; mi++)
            #pragma unroll
            for (int ni = 0; ni < 4; ni++)
                #pragma unroll
                for (int j = 0; j < 4; j++) {
                    int grow = wr * 64 + mi * 16 + g + 8 * (j >> 1);
                    if (grow != 0) {
                        int c = wc * 32 + ni * 8 + 2 * t + (j & 1);
                        float v = __expf(acc[mi][ni][j] * scale) / colsum[c];
                        int qi = mi * 2 + (j >> 1);
                        rm[qi] = fmaxf(rm[qi], v);
                    }
                }
        #pragma unroll
        for (int o = 1; o <= 2; o <<= 1)
            #pragma unroll
            for (int q = 0; q < 8; q++)
                rm[q] = fmaxf(rm[q], __shfl_xor_sync(0xffffffffu, rm[q], o));
        if (t == 0) {
            #pragma unroll
            for (int q = 0; q < 8; q++)
                atomicMax((int*)&rowmax[wr * 64 + (q >> 1) * 16 + g + 8 * (q & 1)],
                          __float_as_int(rm[q]));
        }
        __syncthreads();
        if (tid >= 1 && tid < BM)
            atomicMax((int*)&g_score[b * (Qn - 1) + tid - 1],
                      __float_as_int(rowmax[tid]));
    }
}

// ---------------- per-launch state reset ----------------
__global__ void init_kernel() {
    for (int i = threadIdx.x; i < Bn*(Qn-1); i += 256) g_score[i] = 0.f;
    for (int i = threadIdx.x; i < Bn*Hn*KEEPN; i += 256) g_rowsum[i] = 0.f;
}

// ---------------- top-32 selection (ties -> lower index) ----------------
__global__ void topk_kernel() {
    int b = blockIdx.x;
    int t = threadIdx.x;   // 128
    __shared__ float sv[128];
    __shared__ float rv[128];
    __shared__ int   ri[128];
    sv[t] = (t < Qn-1) ? g_score[b*(Qn-1) + t] : -INFINITY;
    __syncthreads();
    for (int r = 0; r < MQn; r++) {
        rv[t] = sv[t]; ri[t] = t;
        __syncthreads();
        for (int off = 64; off > 0; off >>= 1) {
            if (t < off) {
                float v2 = rv[t+off]; int i2 = ri[t+off];
                if (v2 > rv[t] || (v2 == rv[t] && i2 < ri[t])) { rv[t] = v2; ri[t] = i2; }
            }
            __syncthreads();
        }
        int win = ri[0];
        if (t == 0) g_keep[b*KEEPN + 1 + r] = win + 1;
        if (t == win) sv[t] = -INFINITY;
        __syncthreads();
    }
    if (t == 0) g_keep[b*KEEPN] = 0;
}

// ---------------- gather + competitive softmax (query axis), rowsums ----------------
__global__ void softmax_kernel() {
    int b = blockIdx.z, h = blockIdx.y;
    int k = blockIdx.x * 128 + threadIdx.x;
    __shared__ int   kq[KEEPN];
    __shared__ float rs[KEEPN];
    if (threadIdx.x < KEEPN) {
        kq[threadIdx.x] = g_keep[b*KEEPN + threadIdx.x];
        rs[threadIdx.x] = 0.f;
    }
    __syncthreads();
    const float* base = g_dots + ((size_t)((b*Hn + h) * Qn)) * Kn + k;
    float d[KEEPN];
    float m = -INFINITY;
    #pragma unroll
    for (int j = 0; j < KEEPN; j++) {
        d[j] = base[(size_t)kq[j] * Kn];
        m = fmaxf(m, d[j]);
    }
    float s = 0.f;
    #pragma unroll
    for (int j = 0; j < KEEPN; j++) { d[j] = __expf(d[j] - m); s += d[j]; }
    float inv = 1.f / s;
    float* outp = g_attn + ((size_t)((b*Hn + h) * KEEPN)) * Kn + k;
    int lane = threadIdx.x & 31;
    #pragma unroll
    for (int j = 0; j < KEEPN; j++) {
        float a = d[j] * inv;
        outp[(size_t)j * Kn] = a;
        float w = a;
        #pragma unroll
        for (int o = 16; o > 0; o >>= 1) w += __shfl_xor_sync(0xffffffffu, w, o);
        if (lane == 0) atomicAdd(&rs[j], w);
    }
    __syncthreads();
    if (threadIdx.x < KEEPN)
        atomicAdd(&g_rowsum[(b*Hn + h)*KEEPN + threadIdx.x], rs[threadIdx.x]);
}

// ---------------- key-axis renormalization of S1 ----------------
__global__ void normalize_kernel() {
    int idx = blockIdx.x * 256 + threadIdx.x;
    const int total = Bn*Hn*KEEPN*Dn;
    if (idx >= total) return;
    int r = idx / Dn;
    float inv = 1.f / (g_rowsum[r] + 1e-8f);
    g_s1f[idx] *= inv;
    g_s1e[idx] *= inv;
}

__global__ void finalize_keep_kernel(float* outp) {
    int i = blockIdx.x * 256 + threadIdx.x;
    if (i < Bn*KEEPN) outp[i] = (float)g_keep[i];
}

// ---------------- launch ----------------
extern "C" void kernel_launch(void* const* d_in, const int* in_sizes, int n_in,
                              void* d_out, int out_size) {
    const float* slots     = (const float*)d_in[0];
    const float* slots_enc = (const float*)d_in[1];
    const float* ctx       = (const float*)d_in[2];
    const float* ctx_enc   = (const float*)d_in[3];
    const float* Wq  = (const float*)d_in[4];
    const float* Wk  = (const float*)d_in[5];
    const float* Wf  = (const float*)d_in[6];
    const float* We  = (const float*)d_in[7];
    const float* Wof = (const float*)d_in[8];
    const float* bof = (const float*)d_in[9];
    const float* Woe = (const float*)d_in[10];
    const float* boe = (const float*)d_in[11];
    float* outp = (float*)d_out;

    float *pq, *pk, *pdots, *pattn, *ps1f, *ps1e, *ppref, *ppree;
    cudaGetSymbolAddress((void**)&pq,    g_q);
    cudaGetSymbolAddress((void**)&pk,    g_k);
    cudaGetSymbolAddress((void**)&pdots, g_dots);
    cudaGetSymbolAddress((void**)&pattn, g_attn);
    cudaGetSymbolAddress((void**)&ps1f,  g_s1f);
    cudaGetSymbolAddress((void**)&ps1e,  g_s1e);
    cudaGetSymbolAddress((void**)&ppref, g_pref);
    cudaGetSymbolAddress((void**)&ppree, g_pree);

    const int   ZBIG = 1 << 30;
    dim3 T(256);

    init_kernel<<<1, 256>>>();

    // q = (slots + slots_enc) @ Wq^T    [2048 x 512 x 512]  NT
    mma_gemm<<<dim3(4, 16, 1), T>>>(slots, slots_enc, nullptr, Dn,
        Wq, nullptr, nullptr, Dn, 0, nullptr, nullptr,
        pq, 0, Dn, Bn*Qn, Dn, Dn, 1.f, 1, ZBIG,
        0, 0, 0, 0, 0, 0, 0);

    // k = (ctx + ctx_enc) @ Wk^T        [65536 x 512 x 512]  NT
    mma_gemm<<<dim3(4, 512, 1), T>>>(ctx, ctx_enc, nullptr, Dn,
        Wk, nullptr, nullptr, Dn, 0, nullptr, nullptr,
        pk, 0, Dn, Bn*Kn, Dn, Dn, 1.f, 1, ZBIG,
        0, 0, 0, 0, 0, 0, 0);

    // dots[b,h,q,k] = (q_h/8) . k_h  [128 x 4096 x 64] NT, batched (b,h), fused scoring
    mma_gemm<<<dim3(Kn/128, 1, Bn*Hn), T>>>(pq, nullptr, nullptr, Dn,
        pk, nullptr, nullptr, Dn, 0, nullptr, nullptr,
        pdots, 0, Kn, Qn, Kn, Cn, 0.125f, Hn, ZBIG,
        (long long)Qn*Dn, 64,
        (long long)Kn*Dn, 64,
        (long long)Hn*Qn*Kn, (long long)Qn*Kn, 1);

    topk_kernel   <<<Bn, 128>>>();
    softmax_kernel<<<dim3(Kn/128, Hn, Bn), 128>>>();

    // S1{f,e} = attn_un @ {ctx, ctx_enc}   [264 x 512 x 4096]  NN, paired, batched b
    mma_gemm<<<dim3(4, 3, 2*Bn), T>>>(pattn, nullptr, nullptr, Kn,
        ctx, nullptr, ctx_enc, Dn, 1, nullptr, nullptr,
        ps1f, (long long)(ps1e - ps1f), Dn, Hn*KEEPN, Dn, Kn, 1.f, 1, Bn,
        (long long)Hn*KEEPN*Kn, 0, (long long)Kn*Dn, 0,
        (long long)Hn*KEEPN*Dn, 0, 0);

    normalize_kernel<<<(Bn*Hn*KEEPN*Dn + 255)/256, 256>>>();

    // per-head contraction pair: pre{f,e}[b,j,h*64+c] = S1n{f,e}[b,h,j,:] . W{f,e}[h*64+c,:]
    mma_gemm<<<dim3(1, 1, 2*Bn*Hn), T>>>(ps1f, nullptr, ps1e, Dn,
        Wf, nullptr, We, Dn, 0, nullptr, nullptr,
        ppref, (long long)(ppree - ppref), Dn, KEEPN, Cn, Dn, 1.f, Hn, Bn*Hn,
        (long long)Hn*KEEPN*Dn, (long long)KEEPN*Dn,
        0, (long long)Cn*Dn,
        (long long)KEEPN*Dn, (long long)Cn, 0);

    // output projection pair straight into d_out  [528 x 512 x 512]  NT
    mma_gemm<<<dim3(4, 5, 2), T>>>(ppref, nullptr, ppree, Dn,
        Wof, nullptr, Woe, Dn, 0, bof, boe,
        outp, (long long)Bn*KEEPN*Dn, Dn, Bn*KEEPN, Dn, Dn, 1.f, 1, 1,
        0, 0, 0, 0, 0, 0, 0);

    finalize_keep_kernel<<<3, 256>>>(outp + 2*(size_t)Bn*KEEPN*Dn);
}

// round 6
// speedup vs baseline: 3.2134x; 1.2078x over previous
#include <cuda_runtime.h>
#include <cuda_bf16.h>
#include <math.h>
#include <stdint.h>

#define Bn 16
#define Qn 128
#define Kn 4096
#define Dn 512
#define Hn 8
#define Cn 64
#define MQn 32
#define KEEPN 33   // MQ + 1

#define NELEM_QD ((size_t)Bn*Qn*Dn)
#define NELEM_KD ((size_t)Bn*Kn*Dn)
#define NELEM_DOTS ((size_t)Bn*Hn*Qn*Kn)
#define NELEM_ATT ((size_t)Bn*Hn*KEEPN*Kn)
#define NELEM_S1 ((size_t)Bn*Hn*KEEPN*Dn)
#define NELEM_PRE ((size_t)Bn*KEEPN*Dn)

// ---------------- scratch (device globals; no allocation allowed) ----------------
static __device__ __nv_bfloat16 g_qsum_h[NELEM_QD], g_qsum_l[NELEM_QD];
static __device__ __nv_bfloat16 g_ksum_h[NELEM_KD], g_ksum_l[NELEM_KD];
static __device__ __nv_bfloat16 g_ctxT_h[NELEM_KD], g_ctxT_l[NELEM_KD];    // [B,D,K]
static __device__ __nv_bfloat16 g_ctxeT_h[NELEM_KD], g_ctxeT_l[NELEM_KD];  // [B,D,K]
static __device__ __nv_bfloat16 g_wh[6*512*512], g_wl[6*512*512]; // Wq Wk Wf We Wof Woe
static __device__ __nv_bfloat16 g_qh[NELEM_QD], g_ql[NELEM_QD];
static __device__ __nv_bfloat16 g_kh[NELEM_KD], g_kl[NELEM_KD];
static __device__ float        g_dots[NELEM_DOTS];
static __device__ __nv_bfloat16 g_ath[NELEM_ATT], g_atl[NELEM_ATT];
static __device__ float        g_s1[2][NELEM_S1];                // f=0, e=1
static __device__ __nv_bfloat16 g_s1nh[2][NELEM_S1], g_s1nl[2][NELEM_S1];
static __device__ __nv_bfloat16 g_preh[2][NELEM_PRE], g_prel[2][NELEM_PRE];
static __device__ float g_score[Bn*(Qn-1)];
static __device__ int   g_keep [Bn*KEEPN];
static __device__ float g_rowsum[Bn*Hn*KEEPN];

// ---------------- helpers ----------------
__device__ __forceinline__ uint32_t s2u(const void* p) {
    uint32_t r;
    asm("{ .reg .u64 t; cvta.to.shared.u64 t, %1; cvt.u32.u64 %0, t; }" : "=r"(r) : "l"(p));
    return r;
}
__device__ __forceinline__ void split1(float v, __nv_bfloat16& h, __nv_bfloat16& l) {
    h = __float2bfloat16(v);
    l = __float2bfloat16(v - __bfloat162float(h));
}
__device__ __forceinline__ void mma16(float* d, const uint32_t* a, const uint32_t* b) {
    asm volatile(
        "mma.sync.aligned.m16n8k16.row.col.f32.bf16.bf16.f32 "
        "{%0,%1,%2,%3}, {%4,%5,%6,%7}, {%8,%9}, {%0,%1,%2,%3};"
        : "+f"(d[0]), "+f"(d[1]), "+f"(d[2]), "+f"(d[3])
        : "r"(a[0]), "r"(a[1]), "r"(a[2]), "r"(a[3]), "r"(b[0]), "r"(b[1]));
}
__device__ __forceinline__ void ldsm4(uint32_t& r0, uint32_t& r1, uint32_t& r2, uint32_t& r3,
                                      uint32_t addr) {
    asm volatile("ldmatrix.sync.aligned.m8n8.x4.shared.b16 {%0,%1,%2,%3}, [%4];"
                 : "=r"(r0), "=r"(r1), "=r"(r2), "=r"(r3) : "r"(addr));
}

// ---------------- unified NT split-bf16 GEMM ----------------
// C[r,c] = scale * sum_k (Ah+Al)[r,k] * (Bh+Bl)[c,k]  (3-term: hh + lh + hl)
// All operands are pre-split bf16 hi/lo planes, row-major (NT: B rows = out cols).
// Pairing: z >= zpair -> switch (A*, B*, bias) pointers and offset C by sCpair.
// mode: 0 = fp32 out (+bias), 1 = split bf16 h/l out, 2 = fp32 out + fused scoring.
#define BM 128
#define BN 128
#define BKt 16

__global__ void __launch_bounds__(256, 2) bs_gemm(
    const __nv_bfloat16* __restrict__ Ah, const __nv_bfloat16* __restrict__ Al,
    const __nv_bfloat16* __restrict__ Ahb, const __nv_bfloat16* __restrict__ Alb,
    int lda,
    const __nv_bfloat16* __restrict__ Bh, const __nv_bfloat16* __restrict__ Bl,
    const __nv_bfloat16* __restrict__ Bhb, const __nv_bfloat16* __restrict__ Blb,
    int ldb,
    const float* __restrict__ bias, const float* __restrict__ biasb,
    float* __restrict__ Cf, __nv_bfloat16* __restrict__ CH, __nv_bfloat16* __restrict__ CL,
    long long sCpair, int ldc,
    int nrows, int ncols, int kdim, float scale, int zdiv, int zpair,
    long long sAb, long long sAhh, long long sBb, long long sBhh,
    long long sCb, long long sChh, int mode)
{
    // [stage][plane(Ah,Al,Bh,Bl)][hf][row] ; plane = 4KB
    __shared__ __align__(16) uint4 sbuf[2][4][2][128];
    __shared__ float scoreBuf[BN + BM];

    int z = blockIdx.z;
    if (z >= zpair) {
        z -= zpair;
        if (Ahb) { Ah = Ahb; Al = Alb; }
        if (Bhb) { Bh = Bhb; Bl = Blb; }
        bias = biasb;
        if (Cf) Cf += sCpair;
        if (CH) { CH += sCpair; CL += sCpair; }
    }
    const int b = z / zdiv, h = z - b * zdiv;
    {
        long long ao = (long long)b * sAb + (long long)h * sAhh;
        long long bo = (long long)b * sBb + (long long)h * sBhh;
        long long co = (long long)b * sCb + (long long)h * sChh;
        Ah += ao; Al += ao;
        Bh += bo; Bl += bo;
        if (Cf) Cf += co;
        if (CH) { CH += co; CL += co; }
    }

    const int tid = threadIdx.x, lane = tid & 31, warp = tid >> 5;
    const int wr = warp >> 2, wc = warp & 3;
    const int g = lane >> 2, t = lane & 3;
    const int row0 = blockIdx.y * BM, col0 = blockIdx.x * BN;
    const int lr = tid >> 1, hf = tid & 1;   // loader row / k-half

    float acc[4][4][4];
    #pragma unroll
    for (int mi = 0; mi < 4; mi++)
        #pragma unroll
        for (int ni = 0; ni < 4; ni++)
            #pragma unroll
            for (int j = 0; j < 4; j++) acc[mi][ni][j] = 0.f;

    uint4 rAh, rAl, rBh, rBl;
    const uint4 Z4 = make_uint4(0u, 0u, 0u, 0u);

    auto ld = [&](int k0) {
        long long ao = (long long)(row0 + lr) * lda + k0 + hf * 8;
        if (row0 + lr < nrows) {
            rAh = *(const uint4*)(Ah + ao);
            rAl = *(const uint4*)(Al + ao);
        } else { rAh = Z4; rAl = Z4; }
        long long bo = (long long)(col0 + lr) * ldb + k0 + hf * 8;
        if (col0 + lr < ncols) {
            rBh = *(const uint4*)(Bh + bo);
            rBl = *(const uint4*)(Bl + bo);
        } else { rBh = Z4; rBl = Z4; }
    };
    auto st = [&](int s) {
        sbuf[s][0][hf][lr] = rAh;
        sbuf[s][1][hf][lr] = rAl;
        sbuf[s][2][hf][lr] = rBh;
        sbuf[s][3][hf][lr] = rBl;
    };

    const uint32_t sb0 = s2u(&sbuf[0][0][0][0]);
    // ldmatrix lane address components
    const int a_off = ((lane >> 4) & 1) * 2048 + (((lane >> 3) & 1) * 8 + (lane & 7)) * 16;
    const int bq = lane >> 3;
    const int b_off = (bq & 1) * 2048 + (wc * 32 + (bq >> 1) * 8 + (lane & 7)) * 16;

    auto step = [&](int s) {
        const uint32_t stg = sb0 + s * 16384;
        uint32_t bh4[4][2], bl4[4][2];
        #pragma unroll
        for (int j = 0; j < 2; j++) {
            ldsm4(bh4[2*j][0], bh4[2*j][1], bh4[2*j+1][0], bh4[2*j+1][1],
                  stg + 2 * 4096 + b_off + j * 256);
            ldsm4(bl4[2*j][0], bl4[2*j][1], bl4[2*j+1][0], bl4[2*j+1][1],
                  stg + 3 * 4096 + b_off + j * 256);
        }
        #pragma unroll
        for (int mi = 0; mi < 4; mi++) {
            const uint32_t rowb = (wr * 64 + mi * 16) * 16;
            uint32_t ah4[4], al4[4];
            ldsm4(ah4[0], ah4[1], ah4[2], ah4[3], stg + a_off + rowb);
            ldsm4(al4[0], al4[1], al4[2], al4[3], stg + 4096 + a_off + rowb);
            #pragma unroll
            for (int ni = 0; ni < 4; ni++) {
                mma16(acc[mi][ni], ah4, bh4[ni]);
                mma16(acc[mi][ni], al4, bh4[ni]);
                mma16(acc[mi][ni], ah4, bl4[ni]);
            }
        }
    };

    const int nt = kdim / BKt;
    ld(0); st(0);
    __syncthreads();
    for (int it = 0; it < nt; it++) {
        int cur = it & 1;
        if (it + 1 < nt) ld((it + 1) * BKt);
        step(cur);
        if (it + 1 < nt) { st(cur ^ 1); __syncthreads(); }
    }

    // ---- epilogue
    #pragma unroll
    for (int mi = 0; mi < 4; mi++) {
        #pragma unroll
        for (int ni = 0; ni < 4; ni++) {
            int r = row0 + wr * 64 + mi * 16 + g;
            int c = col0 + wc * 32 + ni * 8 + 2 * t;
            if (c >= ncols) continue;
            #pragma unroll
            for (int jj = 0; jj < 2; jj++) {
                int rr = r + jj * 8;
                if (rr >= nrows) continue;
                float v0 = acc[mi][ni][jj * 2 + 0] * scale;
                float v1 = acc[mi][ni][jj * 2 + 1] * scale;
                if (mode == 1) {
                    __nv_bfloat16 h0, l0, h1, l1;
                    split1(v0, h0, l0); split1(v1, h1, l1);
                    *(__nv_bfloat162*)(CH + (long long)rr * ldc + c) = __halves2bfloat162(h0, h1);
                    *(__nv_bfloat162*)(CL + (long long)rr * ldc + c) = __halves2bfloat162(l0, l1);
                } else {
                    if (bias) { v0 += bias[c]; v1 += bias[c + 1]; }
                    *(float2*)(Cf + (long long)rr * ldc + c) = make_float2(v0, v1);
                }
            }
        }
    }

    // ---- fused query-scoring epilogue (dots only)
    if (mode == 2) {
        float* colsum = scoreBuf;
        float* rowmax = scoreBuf + BN;
        for (int i = tid; i < BN + BM; i += 256) scoreBuf[i] = 0.f;
        __syncthreads();

        float cs[8];
        #pragma unroll
        for (int q = 0; q < 8; q++) cs[q] = 0.f;
        #pragma unroll
        for (int mi = 0; mi < 4; mi++)
            #pragma unroll
            for (int ni = 0; ni < 4; ni++)
                #pragma unroll
                for (int j = 0; j < 4; j++) {
                    int grow = wr * 64 + mi * 16 + g + 8 * (j >> 1);
                    if (grow != 0)
                        cs[ni * 2 + (j & 1)] += __expf(acc[mi][ni][j] * scale);
                }
        #pragma unroll
        for (int o = 4; o <= 16; o <<= 1)
            #pragma unroll
            for (int q = 0; q < 8; q++)
                cs[q] += __shfl_xor_sync(0xffffffffu, cs[q], o);
        if (g == 0) {
            #pragma unroll
            for (int q = 0; q < 8; q++)
                atomicAdd(&colsum[wc * 32 + (q >> 1) * 8 + 2 * t + (q & 1)], cs[q]);
        }
        __syncthreads();

        float rm[8];
        #pragma unroll
        for (int q = 0; q < 8; q++) rm[q] = 0.f;
        #pragma unroll
        for (int mi = 0; mi < 4; mi++)
            #pragma unroll
            for (int ni = 0; ni < 4; ni++)
                #pragma unroll
                for (int j = 0; j < 4; j++) {
                    int grow = wr * 64 + mi * 16 + g + 8 * (j >> 1);
                    if (grow != 0) {
                        int c = wc * 32 + ni * 8 + 2 * t + (j & 1);
                        float v = __expf(acc[mi][ni][j] * scale) / colsum[c];
                        int qi = mi * 2 + (j >> 1);
                        rm[qi] = fmaxf(rm[qi], v);
                    }
                }
        #pragma unroll
        for (int o = 1; o <= 2; o <<= 1)
            #pragma unroll
            for (int q = 0; q < 8; q++)
                rm[q] = fmaxf(rm[q], __shfl_xor_sync(0xffffffffu, rm[q], o));
        if (t == 0) {
            #pragma unroll
            for (int q = 0; q < 8; q++)
                atomicMax((int*)&rowmax[wr * 64 + (q >> 1) * 16 + g + 8 * (q & 1)],
                          __float_as_int(rm[q]));
        }
        __syncthreads();
        if (tid >= 1 && tid < BM)
            atomicMax((int*)&g_score[b * (Qn - 1) + tid - 1],
                      __float_as_int(rowmax[tid]));
    }
}

// ---------------- split / transpose ctx & ctx_enc ----------------
// reads ctx, ctx_enc [B,K,D]; writes ksum h/l [B,K,D] and ctxT/ctxeT h/l [B,D,K]
__global__ void split_ctx_kernel(const float* __restrict__ ctx, const float* __restrict__ ctxe) {
    __shared__ float tc_[32][33], te_[32][33];
    int bb = blockIdx.z, d0 = blockIdx.x * 32, k0 = blockIdx.y * 32;
    int tx = threadIdx.x, ty = threadIdx.y;
    const float* pc = ctx  + ((long long)bb * Kn + k0) * Dn + d0;
    const float* pe = ctxe + ((long long)bb * Kn + k0) * Dn + d0;
    #pragma unroll
    for (int j = 0; j < 4; j++) {
        int kk = ty + j * 8;
        float c = pc[(long long)kk * Dn + tx];
        float e = pe[(long long)kk * Dn + tx];
        tc_[kk][tx] = c; te_[kk][tx] = e;
        __nv_bfloat16 sh, sl;
        split1(c + e, sh, sl);
        long long o = ((long long)bb * Kn + k0 + kk) * Dn + d0 + tx;
        g_ksum_h[o] = sh; g_ksum_l[o] = sl;
    }
    __syncthreads();
    #pragma unroll
    for (int j = 0; j < 4; j++) {
        int dd = ty + j * 8;
        long long o = ((long long)bb * Dn + d0 + dd) * Kn + k0 + tx;
        __nv_bfloat16 hh, ll;
        split1(tc_[tx][dd], hh, ll);
        g_ctxT_h[o] = hh; g_ctxT_l[o] = ll;
        split1(te_[tx][dd], hh, ll);
        g_ctxeT_h[o] = hh; g_ctxeT_l[o] = ll;
    }
}

// ---------------- generic elementwise split (optionally a+b) ----------------
__global__ void split_kernel(const float* __restrict__ a, const float* __restrict__ a2,
                             __nv_bfloat16* __restrict__ oh, __nv_bfloat16* __restrict__ ol,
                             int n) {
    int i = blockIdx.x * 256 + threadIdx.x;
    if (i >= n) return;
    float v = a[i];
    if (a2) v += a2[i];
    __nv_bfloat16 hh, ll;
    split1(v, hh, ll);
    oh[i] = hh; ol[i] = ll;
}

// ---------------- per-launch state reset ----------------
__global__ void init_kernel() {
    for (int i = threadIdx.x; i < Bn*(Qn-1); i += 256) g_score[i] = 0.f;
    for (int i = threadIdx.x; i < Bn*Hn*KEEPN; i += 256) g_rowsum[i] = 0.f;
}

// ---------------- top-32 selection (ties -> lower index) ----------------
__global__ void topk_kernel() {
    int b = blockIdx.x;
    int t = threadIdx.x;   // 128
    __shared__ float sv[128];
    __shared__ float rv[128];
    __shared__ int   ri[128];
    sv[t] = (t < Qn-1) ? g_score[b*(Qn-1) + t] : -INFINITY;
    __syncthreads();
    for (int r = 0; r < MQn; r++) {
        rv[t] = sv[t]; ri[t] = t;
        __syncthreads();
        for (int off = 64; off > 0; off >>= 1) {
            if (t < off) {
                float v2 = rv[t+off]; int i2 = ri[t+off];
                if (v2 > rv[t] || (v2 == rv[t] && i2 < ri[t])) { rv[t] = v2; ri[t] = i2; }
            }
            __syncthreads();
        }
        int win = ri[0];
        if (t == 0) g_keep[b*KEEPN + 1 + r] = win + 1;
        if (t == win) sv[t] = -INFINITY;
        __syncthreads();
    }
    if (t == 0) g_keep[b*KEEPN] = 0;
}

// ---------------- gather + competitive softmax (query axis), split attn + rowsums ----------------
__global__ void softmax_kernel() {
    int b = blockIdx.z, h = blockIdx.y;
    int k = blockIdx.x * 128 + threadIdx.x;
    __shared__ int   kq[KEEPN];
    __shared__ float rs[KEEPN];
    if (threadIdx.x < KEEPN) {
        kq[threadIdx.x] = g_keep[b*KEEPN + threadIdx.x];
        rs[threadIdx.x] = 0.f;
    }
    __syncthreads();
    const float* base = g_dots + ((size_t)((b*Hn + h) * Qn)) * Kn + k;
    float d[KEEPN];
    float m = -INFINITY;
    #pragma unroll
    for (int j = 0; j < KEEPN; j++) {
        d[j] = base[(size_t)kq[j] * Kn];
        m = fmaxf(m, d[j]);
    }
    float s = 0.f;
    #pragma unroll
    for (int j = 0; j < KEEPN; j++) { d[j] = __expf(d[j] - m); s += d[j]; }
    float inv = 1.f / s;
    size_t obase = ((size_t)((b*Hn + h) * KEEPN)) * Kn + k;
    int lane = threadIdx.x & 31;
    #pragma unroll
    for (int j = 0; j < KEEPN; j++) {
        float a = d[j] * inv;
        __nv_bfloat16 hh, ll;
        split1(a, hh, ll);
        g_ath[obase + (size_t)j * Kn] = hh;
        g_atl[obase + (size_t)j * Kn] = ll;
        float w = a;
        #pragma unroll
        for (int o = 16; o > 0; o >>= 1) w += __shfl_xor_sync(0xffffffffu, w, o);
        if (lane == 0) atomicAdd(&rs[j], w);
    }
    __syncthreads();
    if (threadIdx.x < KEEPN)
        atomicAdd(&g_rowsum[(b*Hn + h)*KEEPN + threadIdx.x], rs[threadIdx.x]);
}

// ---------------- key-axis renormalization + split of S1 ----------------
__global__ void normalize_kernel() {
    int idx = blockIdx.x * 256 + threadIdx.x;
    const int half = Bn*Hn*KEEPN*Dn;
    if (idx >= 2 * half) return;
    int p = idx / half;
    int i = idx - p * half;
    int r = i / Dn;
    float inv = 1.f / (g_rowsum[r] + 1e-8f);
    float v = g_s1[p][i] * inv;
    __nv_bfloat16 hh, ll;
    split1(v, hh, ll);
    g_s1nh[p][i] = hh; g_s1nl[p][i] = ll;
}

__global__ void finalize_keep_kernel(float* outp) {
    int i = blockIdx.x * 256 + threadIdx.x;
    if (i < Bn*KEEPN) outp[i] = (float)g_keep[i];
}

// ---------------- launch ----------------
extern "C" void kernel_launch(void* const* d_in, const int* in_sizes, int n_in,
                              void* d_out, int out_size) {
    const float* slots     = (const float*)d_in[0];
    const float* slots_enc = (const float*)d_in[1];
    const float* ctx       = (const float*)d_in[2];
    const float* ctx_enc   = (const float*)d_in[3];
    const float* Wq  = (const float*)d_in[4];
    const float* Wk  = (const float*)d_in[5];
    const float* Wf  = (const float*)d_in[6];
    const float* We  = (const float*)d_in[7];
    const float* Wof = (const float*)d_in[8];
    const float* bof = (const float*)d_in[9];
    const float* Woe = (const float*)d_in[10];
    const float* boe = (const float*)d_in[11];
    float* outp = (float*)d_out;

    __nv_bfloat16 *pqsh, *pqsl, *pksh, *pksl, *pcth, *pctl, *pceh, *pcel;
    __nv_bfloat16 *pwh, *pwl, *pqh, *pql, *pkh, *pkl, *path, *patl;
    __nv_bfloat16 *ps1nh, *ps1nl, *ppreh, *pprel;
    float *pdots, *ps1;
    cudaGetSymbolAddress((void**)&pqsh, g_qsum_h);  cudaGetSymbolAddress((void**)&pqsl, g_qsum_l);
    cudaGetSymbolAddress((void**)&pksh, g_ksum_h);  cudaGetSymbolAddress((void**)&pksl, g_ksum_l);
    cudaGetSymbolAddress((void**)&pcth, g_ctxT_h);  cudaGetSymbolAddress((void**)&pctl, g_ctxT_l);
    cudaGetSymbolAddress((void**)&pceh, g_ctxeT_h); cudaGetSymbolAddress((void**)&pcel, g_ctxeT_l);
    cudaGetSymbolAddress((void**)&pwh, g_wh);       cudaGetSymbolAddress((void**)&pwl, g_wl);
    cudaGetSymbolAddress((void**)&pqh, g_qh);       cudaGetSymbolAddress((void**)&pql, g_ql);
    cudaGetSymbolAddress((void**)&pkh, g_kh);       cudaGetSymbolAddress((void**)&pkl, g_kl);
    cudaGetSymbolAddress((void**)&path, g_ath);     cudaGetSymbolAddress((void**)&patl, g_atl);
    cudaGetSymbolAddress((void**)&ps1nh, g_s1nh);   cudaGetSymbolAddress((void**)&ps1nl, g_s1nl);
    cudaGetSymbolAddress((void**)&ppreh, g_preh);   cudaGetSymbolAddress((void**)&pprel, g_prel);
    cudaGetSymbolAddress((void**)&pdots, g_dots);
    cudaGetSymbolAddress((void**)&ps1, g_s1);

    const int ZBIG = 1 << 30;
    const int WN = 512 * 512;   // one weight matrix
    dim3 T(256);

    init_kernel<<<1, 256>>>();

    // split ctx / ctx_enc -> ksum planes + transposed ctxT/ctxeT planes
    split_ctx_kernel<<<dim3(Dn/32, Kn/32, Bn), dim3(32, 8)>>>(ctx, ctx_enc);

    // qsum = slots + slots_enc
    split_kernel<<<(int)((NELEM_QD + 255)/256), T>>>(slots, slots_enc, pqsh, pqsl, (int)NELEM_QD);
    // weights
    split_kernel<<<(WN+255)/256, T>>>(Wq,  nullptr, pwh + 0*WN, pwl + 0*WN, WN);
    split_kernel<<<(WN+255)/256, T>>>(Wk,  nullptr, pwh + 1*WN, pwl + 1*WN, WN);
    split_kernel<<<(WN+255)/256, T>>>(Wf,  nullptr, pwh + 2*WN, pwl + 2*WN, WN);
    split_kernel<<<(WN+255)/256, T>>>(We,  nullptr, pwh + 3*WN, pwl + 3*WN, WN);
    split_kernel<<<(WN+255)/256, T>>>(Wof, nullptr, pwh + 4*WN, pwl + 4*WN, WN);
    split_kernel<<<(WN+255)/256, T>>>(Woe, nullptr, pwh + 5*WN, pwl + 5*WN, WN);

    // q-proj: [2048 x 512 x 512], split out
    bs_gemm<<<dim3(4, 16, 1), T>>>(pqsh, pqsl, nullptr, nullptr, Dn,
        pwh + 0*WN, pwl + 0*WN, nullptr, nullptr, Dn,
        nullptr, nullptr, nullptr, pqh, pql, 0, Dn,
        Bn*Qn, Dn, Dn, 1.f, 1, ZBIG, 0, 0, 0, 0, 0, 0, 1);

    // k-proj: [65536 x 512 x 512], split out
    bs_gemm<<<dim3(4, 512, 1), T>>>(pksh, pksl, nullptr, nullptr, Dn,
        pwh + 1*WN, pwl + 1*WN, nullptr, nullptr, Dn,
        nullptr, nullptr, nullptr, pkh, pkl, 0, Dn,
        Bn*Kn, Dn, Dn, 1.f, 1, ZBIG, 0, 0, 0, 0, 0, 0, 1);

    // dots: [128 x 4096 x 64] batched (b,h), fp32 out + fused scoring
    bs_gemm<<<dim3(Kn/128, 1, Bn*Hn), T>>>(pqh, pql, nullptr, nullptr, Dn,
        pkh, pkl, nullptr, nullptr, Dn,
        nullptr, nullptr, pdots, nullptr, nullptr, 0, Kn,
        Qn, Kn, Cn, 0.125f, Hn, ZBIG,
        (long long)Qn*Dn, 64, (long long)Kn*Dn, 64,
        (long long)Hn*Qn*Kn, (long long)Qn*Kn, 2);

    topk_kernel   <<<Bn, 128>>>();
    softmax_kernel<<<dim3(Kn/128, Hn, Bn), 128>>>();

    // AV paired: [264 x 512 x 4096] batched b; f: B=ctxT, e: B=ctxeT
    bs_gemm<<<dim3(4, 3, 2*Bn), T>>>(path, patl, nullptr, nullptr, Kn,
        pcth, pctl, pceh, pcel, Kn,
        nullptr, nullptr, ps1, nullptr, nullptr, (long long)NELEM_S1, Dn,
        Hn*KEEPN, Dn, Kn, 1.f, 1, Bn,
        (long long)Hn*KEEPN*Kn, 0, (long long)Dn*Kn, 0,
        (long long)Hn*KEEPN*Dn, 0, 0);

    normalize_kernel<<<(int)((2*NELEM_S1 + 255)/256), T>>>();

    // per-head contraction paired: [33 x 64 x 512] batched (b,h), split out
    bs_gemm<<<dim3(1, 1, 2*Bn*Hn), T>>>(ps1nh, ps1nl, ps1nh + NELEM_S1, ps1nl + NELEM_S1, Dn,
        pwh + 2*WN, pwl + 2*WN, pwh + 3*WN, pwl + 3*WN, Dn,
        nullptr, nullptr, nullptr, ppreh, pprel, (long long)NELEM_PRE, Dn,
        KEEPN, Cn, Dn, 1.f, Hn, Bn*Hn,
        (long long)Hn*KEEPN*Dn, (long long)KEEPN*Dn,
        0, (long long)Cn*Dn,
        (long long)KEEPN*Dn, (long long)Cn, 1);

    // out-proj paired: [528 x 512 x 512] -> d_out
    bs_gemm<<<dim3(4, 5, 2), T>>>(ppreh, pprel, ppreh + NELEM_PRE, pprel + NELEM_PRE, Dn,
        pwh + 4*WN, pwl + 4*WN, pwh + 5*WN, pwl + 5*WN, Dn,
        bof, boe, outp, nullptr, nullptr, (long long)Bn*KEEPN*Dn, Dn,
        Bn*KEEPN, Dn, Dn, 1.f, 1, 1,
        0, 0, 0, 0, 0, 0, 0);

    finalize_keep_kernel<<<3, 256>>>(outp + 2*(size_t)Bn*KEEPN*Dn);
}